// round 1
// baseline (speedup 1.0000x reference)
#include <cuda_runtime.h>
#include <math.h>

#define BATCH 4
#define SEQ   2048
#define DM    1024
#define NH    16
#define HD    64
#define MROWS (BATCH*SEQ)      // 8192
#define NBH   (BATCH*NH)       // 64

// ---------------- scratch (device globals: allocation-free rule) -------------
__device__ float g_q[(size_t)NBH * SEQ * HD];      // [bh, s, 64]
__device__ float g_k[(size_t)NBH * SEQ * HD];
__device__ float g_v[(size_t)NBH * SEQ * HD];
__device__ float g_scores[(size_t)NBH * SEQ * SEQ]; // [bh, qi, kj]  ~1.07GB
__device__ float g_ctx[(size_t)MROWS * DM];         // [b, s, h*64+d]

// =============================================================================
// Kernel 1: fused QKV projection.  Y = X @ W{q,k,v} + b, permuted to [bh,s,64]
// X: [8192, 1024] row-major. W: [1024, 1024]. blockIdx.z in {0,1,2}.
// Tile: BM=BN=64, BK=16, 256 threads, 4x4 micro-tile.
// =============================================================================
__global__ __launch_bounds__(256) void k_proj_qkv(
    const float* __restrict__ X,
    const float* __restrict__ Wq, const float* __restrict__ bq,
    const float* __restrict__ Wk, const float* __restrict__ bk,
    const float* __restrict__ Wv, const float* __restrict__ bv)
{
    const int which = blockIdx.z;
    const float* __restrict__ W    = (which == 0) ? Wq : (which == 1) ? Wk : Wv;
    const float* __restrict__ bias = (which == 0) ? bq : (which == 1) ? bk : bv;
    float* __restrict__ out        = (which == 0) ? g_q : (which == 1) ? g_k : g_v;

    const int bm = blockIdx.y * 64;
    const int bn = blockIdx.x * 64;
    const int tid = threadIdx.x;

    __shared__ float As[16][64];   // As[k][row]
    __shared__ float Bs[16][64];   // Bs[k][col]

    const int ar = tid >> 2;             // 0..63
    const int ak = (tid & 3) * 4;        // 0,4,8,12
    const int br = tid >> 4;             // 0..15
    const int bc = (tid & 15) * 4;       // 0..60

    const int ty = tid >> 4;             // 0..15
    const int tx = tid & 15;             // 0..15

    float acc[4][4];
#pragma unroll
    for (int i = 0; i < 4; i++)
#pragma unroll
        for (int j = 0; j < 4; j++) acc[i][j] = 0.f;

    for (int k0 = 0; k0 < DM; k0 += 16) {
        float4 av = *(const float4*)&X[(size_t)(bm + ar) * DM + k0 + ak];
        As[ak + 0][ar] = av.x; As[ak + 1][ar] = av.y;
        As[ak + 2][ar] = av.z; As[ak + 3][ar] = av.w;
        float4 bv4 = *(const float4*)&W[(size_t)(k0 + br) * DM + bn + bc];
        *(float4*)&Bs[br][bc] = bv4;
        __syncthreads();
#pragma unroll
        for (int kk = 0; kk < 16; kk++) {
            float4 a = *(const float4*)&As[kk][ty * 4];
            float4 b = *(const float4*)&Bs[kk][tx * 4];
            float aa[4] = {a.x, a.y, a.z, a.w};
            float bb[4] = {b.x, b.y, b.z, b.w};
#pragma unroll
            for (int i = 0; i < 4; i++)
#pragma unroll
                for (int j = 0; j < 4; j++) acc[i][j] = fmaf(aa[i], bb[j], acc[i][j]);
        }
        __syncthreads();
    }

    // epilogue: permuted store to [bh, s, 64]
#pragma unroll
    for (int i = 0; i < 4; i++) {
        const int row = bm + ty * 4 + i;
        const int b   = row >> 11;          // /2048
        const int s   = row & 2047;
#pragma unroll
        for (int j = 0; j < 4; j++) {
            const int col = bn + tx * 4 + j;
            const int h   = col >> 6;
            const int dh  = col & 63;
            const float v = acc[i][j] + bias[col];
            out[(((size_t)(b * NH + h)) * SEQ + s) * HD + dh] = v;
        }
    }
}

// =============================================================================
// Kernel 2: scores[bh] = (Q[bh] @ K[bh]^T) * scale, causal masked.
// Per bh: M=N=2048, K=64.  Upper-triangle blocks skipped entirely.
// =============================================================================
__global__ __launch_bounds__(256) void k_scores()
{
    const int bh = blockIdx.z;
    const int bm = blockIdx.y * 64;   // query rows
    const int bn = blockIdx.x * 64;   // kv cols
    if (bn > bm) return;              // fully masked block: never read downstream

    const float* __restrict__ Q = g_q + (size_t)bh * SEQ * HD;
    const float* __restrict__ K = g_k + (size_t)bh * SEQ * HD;
    float* __restrict__ Sc = g_scores + (size_t)bh * SEQ * SEQ;

    const int tid = threadIdx.x;
    __shared__ float As[16][64];  // q^T tile
    __shared__ float Bs[16][64];  // k^T tile

    const int ar = tid >> 2;  const int ak = (tid & 3) * 4;
    const int cc = tid >> 2;  const int ck = (tid & 3) * 4;
    const int ty = tid >> 4;  const int tx = tid & 15;

    float acc[4][4];
#pragma unroll
    for (int i = 0; i < 4; i++)
#pragma unroll
        for (int j = 0; j < 4; j++) acc[i][j] = 0.f;

    for (int k0 = 0; k0 < HD; k0 += 16) {
        float4 av = *(const float4*)&Q[(size_t)(bm + ar) * HD + k0 + ak];
        As[ak + 0][ar] = av.x; As[ak + 1][ar] = av.y;
        As[ak + 2][ar] = av.z; As[ak + 3][ar] = av.w;
        float4 kv = *(const float4*)&K[(size_t)(bn + cc) * HD + k0 + ck];
        Bs[ck + 0][cc] = kv.x; Bs[ck + 1][cc] = kv.y;
        Bs[ck + 2][cc] = kv.z; Bs[ck + 3][cc] = kv.w;
        __syncthreads();
#pragma unroll
        for (int kk = 0; kk < 16; kk++) {
            float4 a = *(const float4*)&As[kk][ty * 4];
            float4 b = *(const float4*)&Bs[kk][tx * 4];
            float aa[4] = {a.x, a.y, a.z, a.w};
            float bb[4] = {b.x, b.y, b.z, b.w};
#pragma unroll
            for (int i = 0; i < 4; i++)
#pragma unroll
                for (int j = 0; j < 4; j++) acc[i][j] = fmaf(aa[i], bb[j], acc[i][j]);
        }
        __syncthreads();
    }

    const float scale = 1.0f / 32.0f;   // 1/sqrt(1024)
#pragma unroll
    for (int i = 0; i < 4; i++) {
        const int qi = bm + ty * 4 + i;
#pragma unroll
        for (int j = 0; j < 4; j++) {
            const int kj = bn + tx * 4 + j;
            float v = acc[i][j] * scale;
            if (kj > qi) v = -INFINITY;
            Sc[(size_t)qi * SEQ + kj] = v;
        }
    }
}

// =============================================================================
// Kernel 3: row softmax over j<=qi ; zero-fill j>qi.  One block per row.
// =============================================================================
__global__ __launch_bounds__(256) void k_softmax()
{
    const int qi = blockIdx.x;
    const int bh = blockIdx.y;
    float* __restrict__ row = g_scores + (size_t)bh * SEQ * SEQ + (size_t)qi * SEQ;
    const int n = qi + 1;
    const int tid = threadIdx.x;

    __shared__ float buf[SEQ];
    __shared__ float red[256];

    float lmax = -INFINITY;
    for (int j = tid; j < n; j += 256) {
        float v = row[j];
        buf[j] = v;
        lmax = fmaxf(lmax, v);
    }
    red[tid] = lmax;
    __syncthreads();
    for (int s = 128; s > 0; s >>= 1) {
        if (tid < s) red[tid] = fmaxf(red[tid], red[tid + s]);
        __syncthreads();
    }
    const float m = red[0];
    __syncthreads();

    float lsum = 0.f;
    for (int j = tid; j < n; j += 256) {
        float e = expf(buf[j] - m);
        buf[j] = e;
        lsum += e;
    }
    red[tid] = lsum;
    __syncthreads();
    for (int s = 128; s > 0; s >>= 1) {
        if (tid < s) red[tid] += red[tid + s];
        __syncthreads();
    }
    const float inv = 1.0f / red[0];
    __syncthreads();

    for (int j = tid; j < SEQ; j += 256)
        row[j] = (j < n) ? buf[j] * inv : 0.f;
}

// =============================================================================
// Kernel 4: ctx[bh] = P[bh] @ V[bh].  M=2048, N=64, K truncated at diagonal.
// Output written to [b, s, h*64+d] layout for the final projection.
// =============================================================================
__global__ __launch_bounds__(256) void k_ctx()
{
    const int bh = blockIdx.z;
    const int bm = blockIdx.y * 64;
    const int kmax = bm + 64;                  // causal: p==0 beyond row index

    const float* __restrict__ P = g_scores + (size_t)bh * SEQ * SEQ;
    const float* __restrict__ V = g_v + (size_t)bh * SEQ * HD;

    const int tid = threadIdx.x;
    __shared__ float As[16][64];
    __shared__ float Bs[16][64];

    const int ar = tid >> 2;  const int ak = (tid & 3) * 4;
    const int br = tid >> 4;  const int bc = (tid & 15) * 4;
    const int ty = tid >> 4;  const int tx = tid & 15;

    float acc[4][4];
#pragma unroll
    for (int i = 0; i < 4; i++)
#pragma unroll
        for (int j = 0; j < 4; j++) acc[i][j] = 0.f;

    for (int k0 = 0; k0 < kmax; k0 += 16) {
        float4 av = *(const float4*)&P[(size_t)(bm + ar) * SEQ + k0 + ak];
        As[ak + 0][ar] = av.x; As[ak + 1][ar] = av.y;
        As[ak + 2][ar] = av.z; As[ak + 3][ar] = av.w;
        float4 bv4 = *(const float4*)&V[(size_t)(k0 + br) * HD + bc];
        *(float4*)&Bs[br][bc] = bv4;
        __syncthreads();
#pragma unroll
        for (int kk = 0; kk < 16; kk++) {
            float4 a = *(const float4*)&As[kk][ty * 4];
            float4 b = *(const float4*)&Bs[kk][tx * 4];
            float aa[4] = {a.x, a.y, a.z, a.w};
            float bb[4] = {b.x, b.y, b.z, b.w};
#pragma unroll
            for (int i = 0; i < 4; i++)
#pragma unroll
                for (int j = 0; j < 4; j++) acc[i][j] = fmaf(aa[i], bb[j], acc[i][j]);
        }
        __syncthreads();
    }

    const int b = bh >> 4;
    const int h = bh & 15;
#pragma unroll
    for (int i = 0; i < 4; i++) {
        const int s = bm + ty * 4 + i;
#pragma unroll
        for (int j = 0; j < 4; j++) {
            const int d = tx * 4 + j;
            g_ctx[((size_t)(b * SEQ + s)) * DM + h * HD + d] = acc[i][j];
        }
    }
}

// =============================================================================
// Kernel 5: out = ctx @ Wo + bo.  M=8192, N=K=1024. Plain row-major out.
// =============================================================================
__global__ __launch_bounds__(256) void k_proj_out(
    const float* __restrict__ Wo, const float* __restrict__ bo,
    float* __restrict__ out)
{
    const int bm = blockIdx.y * 64;
    const int bn = blockIdx.x * 64;
    const int tid = threadIdx.x;

    __shared__ float As[16][64];
    __shared__ float Bs[16][64];

    const int ar = tid >> 2;  const int ak = (tid & 3) * 4;
    const int br = tid >> 4;  const int bc = (tid & 15) * 4;
    const int ty = tid >> 4;  const int tx = tid & 15;

    float acc[4][4];
#pragma unroll
    for (int i = 0; i < 4; i++)
#pragma unroll
        for (int j = 0; j < 4; j++) acc[i][j] = 0.f;

    for (int k0 = 0; k0 < DM; k0 += 16) {
        float4 av = *(const float4*)&g_ctx[(size_t)(bm + ar) * DM + k0 + ak];
        As[ak + 0][ar] = av.x; As[ak + 1][ar] = av.y;
        As[ak + 2][ar] = av.z; As[ak + 3][ar] = av.w;
        float4 bv4 = *(const float4*)&Wo[(size_t)(k0 + br) * DM + bn + bc];
        *(float4*)&Bs[br][bc] = bv4;
        __syncthreads();
#pragma unroll
        for (int kk = 0; kk < 16; kk++) {
            float4 a = *(const float4*)&As[kk][ty * 4];
            float4 b = *(const float4*)&Bs[kk][tx * 4];
            float aa[4] = {a.x, a.y, a.z, a.w};
            float bb[4] = {b.x, b.y, b.z, b.w};
#pragma unroll
            for (int i = 0; i < 4; i++)
#pragma unroll
                for (int j = 0; j < 4; j++) acc[i][j] = fmaf(aa[i], bb[j], acc[i][j]);
        }
        __syncthreads();
    }

#pragma unroll
    for (int i = 0; i < 4; i++) {
        const int row = bm + ty * 4 + i;
#pragma unroll
        for (int j = 0; j < 4; j++) {
            const int col = bn + tx * 4 + j;
            out[(size_t)row * DM + col] = acc[i][j] + bo[col];
        }
    }
}

// =============================================================================
extern "C" void kernel_launch(void* const* d_in, const int* in_sizes, int n_in,
                              void* d_out, int out_size)
{
    (void)in_sizes; (void)n_in; (void)out_size;
    const float* x  = (const float*)d_in[0];
    const float* Wq = (const float*)d_in[1];
    const float* bq = (const float*)d_in[2];
    const float* Wk = (const float*)d_in[3];
    const float* bk = (const float*)d_in[4];
    const float* Wv = (const float*)d_in[5];
    const float* bv = (const float*)d_in[6];
    const float* Wo = (const float*)d_in[7];
    const float* bo = (const float*)d_in[8];
    float* out = (float*)d_out;

    // 1) QKV projections
    {
        dim3 grid(DM / 64, MROWS / 64, 3);
        k_proj_qkv<<<grid, 256>>>(x, Wq, bq, Wk, bk, Wv, bv);
    }
    // 2) scores
    {
        dim3 grid(SEQ / 64, SEQ / 64, NBH);
        k_scores<<<grid, 256>>>();
    }
    // 3) softmax
    {
        dim3 grid(SEQ, NBH);
        k_softmax<<<grid, 256>>>();
    }
    // 4) ctx
    {
        dim3 grid(1, SEQ / 64, NBH);
        k_ctx<<<grid, 256>>>();
    }
    // 5) output projection
    {
        dim3 grid(DM / 64, MROWS / 64, 1);
        k_proj_out<<<grid, 256>>>(Wo, bo, out);
    }
}

// round 2
// speedup vs baseline: 1.2991x; 1.2991x over previous
#include <cuda_runtime.h>
#include <math.h>

#define BATCH 4
#define SEQ   2048
#define DM    1024
#define NH    16
#define HD    64
#define MROWS (BATCH*SEQ)      // 8192
#define NBH   (BATCH*NH)       // 64

// ---------------- scratch (device globals: allocation-free rule) -------------
__device__ float g_q[(size_t)NBH * SEQ * HD];      // [bh, s, 64]
__device__ float g_k[(size_t)NBH * SEQ * HD];
__device__ float g_v[(size_t)NBH * SEQ * HD];
__device__ float g_ctx[(size_t)MROWS * DM];        // [b, s, h*64+d]

// =============================================================================
// Kernel 1: fused QKV projection, 128x128 tile, BK=16, 8x8 micro, reg prefetch.
// Y = X @ W{q,k,v} + b, permuted to [bh, s, 64].  blockIdx.z in {0,1,2}.
// =============================================================================
__global__ __launch_bounds__(256, 2) void k_proj_qkv(
    const float* __restrict__ X,
    const float* __restrict__ Wq, const float* __restrict__ bq,
    const float* __restrict__ Wk, const float* __restrict__ bk,
    const float* __restrict__ Wv, const float* __restrict__ bv)
{
    const int which = blockIdx.z;
    const float* __restrict__ W    = (which == 0) ? Wq : (which == 1) ? Wk : Wv;
    const float* __restrict__ bias = (which == 0) ? bq : (which == 1) ? bk : bv;
    float* __restrict__ out        = (which == 0) ? g_q : (which == 1) ? g_k : g_v;

    const int bm = blockIdx.y * 128;
    const int bn = blockIdx.x * 128;
    const int tid = threadIdx.x;
    const int ty = tid >> 4, tx = tid & 15;

    __shared__ float As[16 * 128];   // As[k][m]
    __shared__ float Bs[16 * 128];   // Bs[k][n]

    // loaders
    const int ar  = tid >> 2;          // 0..63   (rows ar, ar+64)
    const int ac4 = (tid & 3) * 4;     // k-offset 0,4,8,12
    const int br  = tid >> 5;          // 0..7    (k-rows br, br+8)
    const int bc4 = (tid & 31) * 4;    // col 0..124

    const float* Ap0 = X + (size_t)(bm + ar) * DM + ac4;
    const float* Ap1 = Ap0 + (size_t)64 * DM;
    const float* Bp0 = W + (size_t)br * DM + bn + bc4;
    const float* Bp1 = Bp0 + (size_t)8 * DM;

    float4 a0 = *(const float4*)Ap0;
    float4 a1 = *(const float4*)Ap1;
    float4 b0 = *(const float4*)Bp0;
    float4 b1 = *(const float4*)Bp1;

    float acc[8][8];
#pragma unroll
    for (int i = 0; i < 8; i++)
#pragma unroll
        for (int j = 0; j < 8; j++) acc[i][j] = 0.f;

    for (int k0 = 0; k0 < DM; k0 += 16) {
        // commit staged tile to smem
        As[(ac4 + 0) * 128 + ar] = a0.x;
        As[(ac4 + 1) * 128 + ar] = a0.y;
        As[(ac4 + 2) * 128 + ar] = a0.z;
        As[(ac4 + 3) * 128 + ar] = a0.w;
        As[(ac4 + 0) * 128 + ar + 64] = a1.x;
        As[(ac4 + 1) * 128 + ar + 64] = a1.y;
        As[(ac4 + 2) * 128 + ar + 64] = a1.z;
        As[(ac4 + 3) * 128 + ar + 64] = a1.w;
        *(float4*)&Bs[br * 128 + bc4]       = b0;
        *(float4*)&Bs[(br + 8) * 128 + bc4] = b1;
        __syncthreads();

        const bool more = (k0 + 16) < DM;
        if (more) {  // prefetch next tile into regs while computing
            a0 = *(const float4*)(Ap0 + k0 + 16);
            a1 = *(const float4*)(Ap1 + k0 + 16);
            b0 = *(const float4*)(Bp0 + (size_t)(k0 + 16) * DM);
            b1 = *(const float4*)(Bp1 + (size_t)(k0 + 16) * DM);
        }

#pragma unroll
        for (int kk = 0; kk < 16; kk++) {
            float4 xa0 = *(const float4*)&As[kk * 128 + ty * 4];
            float4 xa1 = *(const float4*)&As[kk * 128 + ty * 4 + 64];
            float4 xb0 = *(const float4*)&Bs[kk * 128 + tx * 4];
            float4 xb1 = *(const float4*)&Bs[kk * 128 + tx * 4 + 64];
            float av[8] = {xa0.x, xa0.y, xa0.z, xa0.w, xa1.x, xa1.y, xa1.z, xa1.w};
            float bv4[8] = {xb0.x, xb0.y, xb0.z, xb0.w, xb1.x, xb1.y, xb1.z, xb1.w};
#pragma unroll
            for (int i = 0; i < 8; i++)
#pragma unroll
                for (int j = 0; j < 8; j++) acc[i][j] = fmaf(av[i], bv4[j], acc[i][j]);
        }
        __syncthreads();
    }

    // epilogue: bias + permuted store [bh, s, 64], float4 stores
    float bb[8];
#pragma unroll
    for (int jh = 0; jh < 2; jh++)
#pragma unroll
        for (int j = 0; j < 4; j++) bb[jh * 4 + j] = bias[bn + jh * 64 + tx * 4 + j];

#pragma unroll
    for (int ih = 0; ih < 2; ih++) {
#pragma unroll
        for (int i = 0; i < 4; i++) {
            const int row = bm + ih * 64 + ty * 4 + i;
            const int b   = row >> 11;
            const int s   = row & 2047;
#pragma unroll
            for (int jh = 0; jh < 2; jh++) {
                const int col = bn + jh * 64 + tx * 4;
                const int h   = col >> 6;
                const int dh  = col & 63;   // = tx*4
                float4 v;
                v.x = acc[ih * 4 + i][jh * 4 + 0] + bb[jh * 4 + 0];
                v.y = acc[ih * 4 + i][jh * 4 + 1] + bb[jh * 4 + 1];
                v.z = acc[ih * 4 + i][jh * 4 + 2] + bb[jh * 4 + 2];
                v.w = acc[ih * 4 + i][jh * 4 + 3] + bb[jh * 4 + 3];
                *(float4*)&out[(((size_t)(b * NH + h)) * SEQ + s) * HD + dh] = v;
            }
        }
    }
}

// =============================================================================
// Kernel 2: fused flash attention (scores + online softmax + P@V), fp32.
// One block per (bh, q-tile of 64).  K/V tiles streamed; S staged in K buffer.
// =============================================================================
#define ST_PITCH 68
#define ATT_SMEM_FLOATS (64*64 + 64*ST_PITCH + 64*64 + 4*64 + 3*64)

__global__ __launch_bounds__(256) void k_attn()
{
    extern __shared__ float sm[];
    float* Qt   = sm;                      // [d=64][m=64]
    float* KtSt = sm + 64 * 64;            // Kt[d][n] pitch 68 / reused as St[n][m]
    float* Vs   = KtSt + 64 * ST_PITCH;    // [n=64][d=64]
    float* red  = Vs + 64 * 64;            // [4][64]
    float* mrow = red + 4 * 64;            // [64]
    float* lrow = mrow + 64;               // [64]
    float* srow = lrow + 64;               // [64]

    const int bh = blockIdx.y;
    const int qb = (int)gridDim.x - 1 - (int)blockIdx.x;   // heavy blocks first
    const int tid = threadIdx.x;
    const int ty = tid >> 4, tx = tid & 15;

    const float* __restrict__ Qg = g_q + (size_t)bh * SEQ * HD;
    const float* __restrict__ Kg = g_k + (size_t)bh * SEQ * HD;
    const float* __restrict__ Vg = g_v + (size_t)bh * SEQ * HD;

    // load Q tile transposed: Qt[d][m]
    {
        const int m  = tid >> 2;
        const int d0 = (tid & 3) * 16;
        const float* src = Qg + (size_t)(qb * 64 + m) * HD + d0;
#pragma unroll
        for (int u = 0; u < 4; u++) {
            float4 v = *(const float4*)(src + u * 4);
            Qt[(d0 + u * 4 + 0) * 64 + m] = v.x;
            Qt[(d0 + u * 4 + 1) * 64 + m] = v.y;
            Qt[(d0 + u * 4 + 2) * 64 + m] = v.z;
            Qt[(d0 + u * 4 + 3) * 64 + m] = v.w;
        }
    }
    if (tid < 64) { mrow[tid] = -INFINITY; lrow[tid] = 0.f; }

    float o[4][4];
#pragma unroll
    for (int i = 0; i < 4; i++)
#pragma unroll
        for (int j = 0; j < 4; j++) o[i][j] = 0.f;

    const int c  = tid >> 6;     // softmax column-chunk 0..3
    const int ms = tid & 63;     // softmax row

    for (int kb = 0; kb <= qb; kb++) {
        __syncthreads();   // prior-iter GEMM2 done (and Q load on iter 0)

        // load K transposed (Kt[d][n], pitch 68) + V natural (Vs[n][d])
        {
            const int n  = tid >> 2;
            const int d0 = (tid & 3) * 16;
            const float* ks = Kg + (size_t)(kb * 64 + n) * HD + d0;
            const float* vp = Vg + (size_t)(kb * 64 + n) * HD + d0;
#pragma unroll
            for (int u = 0; u < 4; u++) {
                float4 kv = *(const float4*)(ks + u * 4);
                KtSt[(d0 + u * 4 + 0) * ST_PITCH + n] = kv.x;
                KtSt[(d0 + u * 4 + 1) * ST_PITCH + n] = kv.y;
                KtSt[(d0 + u * 4 + 2) * ST_PITCH + n] = kv.z;
                KtSt[(d0 + u * 4 + 3) * ST_PITCH + n] = kv.w;
                *(float4*)&Vs[n * 64 + d0 + u * 4] = *(const float4*)(vp + u * 4);
            }
        }
        __syncthreads();

        // GEMM1: S = Q @ K^T  (4x4 per thread)
        float s[4][4];
#pragma unroll
        for (int i = 0; i < 4; i++)
#pragma unroll
            for (int j = 0; j < 4; j++) s[i][j] = 0.f;
#pragma unroll 8
        for (int kk = 0; kk < 64; kk++) {
            float4 a = *(const float4*)&Qt[kk * 64 + ty * 4];
            float4 b = *(const float4*)&KtSt[kk * ST_PITCH + tx * 4];
            float av[4] = {a.x, a.y, a.z, a.w};
            float bv4[4] = {b.x, b.y, b.z, b.w};
#pragma unroll
            for (int i = 0; i < 4; i++)
#pragma unroll
                for (int j = 0; j < 4; j++) s[i][j] = fmaf(av[i], bv4[j], s[i][j]);
        }
        __syncthreads();   // all reads of Kt done before overwrite as St

        // scale + causal mask + transposed store  St[n][m]
        const float SC = 1.0f / 32.0f;
        const bool diag = (kb == qb);
#pragma unroll
        for (int i = 0; i < 4; i++) {
#pragma unroll
            for (int j = 0; j < 4; j++) {
                float v = s[i][j] * SC;
                if (diag && (tx * 4 + j) > (ty * 4 + i)) v = -INFINITY;
                KtSt[(tx * 4 + j) * ST_PITCH + ty * 4 + i] = v;
            }
        }
        __syncthreads();

        // online softmax: 4 threads per row
        float pm = -INFINITY;
#pragma unroll
        for (int u = 0; u < 16; u++)
            pm = fmaxf(pm, KtSt[(c * 16 + u) * ST_PITCH + ms]);
        red[c * 64 + ms] = pm;
        __syncthreads();
        if (c == 0) {
            float t = fmaxf(fmaxf(red[ms], red[64 + ms]), fmaxf(red[128 + ms], red[192 + ms]));
            float mo = mrow[ms];
            float mn = fmaxf(mo, t);
            srow[ms] = __expf(mo - mn);
            mrow[ms] = mn;
        }
        __syncthreads();
        const float mn = mrow[ms];
        float ps = 0.f;
#pragma unroll
        for (int u = 0; u < 16; u++) {
            const int idx = (c * 16 + u) * ST_PITCH + ms;
            float p = __expf(KtSt[idx] - mn);
            KtSt[idx] = p;
            ps += p;
        }
        red[c * 64 + ms] = ps;
        __syncthreads();
        if (c == 0)
            lrow[ms] = lrow[ms] * srow[ms] + (red[ms] + red[64 + ms] + red[128 + ms] + red[192 + ms]);
        __syncthreads();

        // GEMM2: O = O*scale + P @ V
        float sc[4];
#pragma unroll
        for (int i = 0; i < 4; i++) sc[i] = srow[ty * 4 + i];
#pragma unroll
        for (int i = 0; i < 4; i++)
#pragma unroll
            for (int j = 0; j < 4; j++) o[i][j] *= sc[i];
#pragma unroll 8
        for (int n = 0; n < 64; n++) {
            float4 a = *(const float4*)&KtSt[n * ST_PITCH + ty * 4];
            float4 b = *(const float4*)&Vs[n * 64 + tx * 4];
            float av[4] = {a.x, a.y, a.z, a.w};
            float bv4[4] = {b.x, b.y, b.z, b.w};
#pragma unroll
            for (int i = 0; i < 4; i++)
#pragma unroll
                for (int j = 0; j < 4; j++) o[i][j] = fmaf(av[i], bv4[j], o[i][j]);
        }
    }
    __syncthreads();

    // epilogue: normalize, write ctx in [b, s, h*64+d] layout
    const int b = bh >> 4, h = bh & 15;
#pragma unroll
    for (int i = 0; i < 4; i++) {
        const float inv = 1.0f / lrow[ty * 4 + i];
        const int srw = qb * 64 + ty * 4 + i;
        float4 v;
        v.x = o[i][0] * inv; v.y = o[i][1] * inv;
        v.z = o[i][2] * inv; v.w = o[i][3] * inv;
        *(float4*)&g_ctx[((size_t)(b * SEQ + srw)) * DM + h * HD + tx * 4] = v;
    }
}

// =============================================================================
// Kernel 3: out = ctx @ Wo + bo.  Same 128x128 GEMM, plain epilogue.
// =============================================================================
__global__ __launch_bounds__(256, 2) void k_proj_out(
    const float* __restrict__ Wo, const float* __restrict__ bo,
    float* __restrict__ out)
{
    const int bm = blockIdx.y * 128;
    const int bn = blockIdx.x * 128;
    const int tid = threadIdx.x;
    const int ty = tid >> 4, tx = tid & 15;

    __shared__ float As[16 * 128];
    __shared__ float Bs[16 * 128];

    const int ar  = tid >> 2;
    const int ac4 = (tid & 3) * 4;
    const int br  = tid >> 5;
    const int bc4 = (tid & 31) * 4;

    const float* Ap0 = g_ctx + (size_t)(bm + ar) * DM + ac4;
    const float* Ap1 = Ap0 + (size_t)64 * DM;
    const float* Bp0 = Wo + (size_t)br * DM + bn + bc4;
    const float* Bp1 = Bp0 + (size_t)8 * DM;

    float4 a0 = *(const float4*)Ap0;
    float4 a1 = *(const float4*)Ap1;
    float4 b0 = *(const float4*)Bp0;
    float4 b1 = *(const float4*)Bp1;

    float acc[8][8];
#pragma unroll
    for (int i = 0; i < 8; i++)
#pragma unroll
        for (int j = 0; j < 8; j++) acc[i][j] = 0.f;

    for (int k0 = 0; k0 < DM; k0 += 16) {
        As[(ac4 + 0) * 128 + ar] = a0.x;
        As[(ac4 + 1) * 128 + ar] = a0.y;
        As[(ac4 + 2) * 128 + ar] = a0.z;
        As[(ac4 + 3) * 128 + ar] = a0.w;
        As[(ac4 + 0) * 128 + ar + 64] = a1.x;
        As[(ac4 + 1) * 128 + ar + 64] = a1.y;
        As[(ac4 + 2) * 128 + ar + 64] = a1.z;
        As[(ac4 + 3) * 128 + ar + 64] = a1.w;
        *(float4*)&Bs[br * 128 + bc4]       = b0;
        *(float4*)&Bs[(br + 8) * 128 + bc4] = b1;
        __syncthreads();

        const bool more = (k0 + 16) < DM;
        if (more) {
            a0 = *(const float4*)(Ap0 + k0 + 16);
            a1 = *(const float4*)(Ap1 + k0 + 16);
            b0 = *(const float4*)(Bp0 + (size_t)(k0 + 16) * DM);
            b1 = *(const float4*)(Bp1 + (size_t)(k0 + 16) * DM);
        }

#pragma unroll
        for (int kk = 0; kk < 16; kk++) {
            float4 xa0 = *(const float4*)&As[kk * 128 + ty * 4];
            float4 xa1 = *(const float4*)&As[kk * 128 + ty * 4 + 64];
            float4 xb0 = *(const float4*)&Bs[kk * 128 + tx * 4];
            float4 xb1 = *(const float4*)&Bs[kk * 128 + tx * 4 + 64];
            float av[8] = {xa0.x, xa0.y, xa0.z, xa0.w, xa1.x, xa1.y, xa1.z, xa1.w};
            float bv4[8] = {xb0.x, xb0.y, xb0.z, xb0.w, xb1.x, xb1.y, xb1.z, xb1.w};
#pragma unroll
            for (int i = 0; i < 8; i++)
#pragma unroll
                for (int j = 0; j < 8; j++) acc[i][j] = fmaf(av[i], bv4[j], acc[i][j]);
        }
        __syncthreads();
    }

    float bb[8];
#pragma unroll
    for (int jh = 0; jh < 2; jh++)
#pragma unroll
        for (int j = 0; j < 4; j++) bb[jh * 4 + j] = bo[bn + jh * 64 + tx * 4 + j];

#pragma unroll
    for (int ih = 0; ih < 2; ih++) {
#pragma unroll
        for (int i = 0; i < 4; i++) {
            const int row = bm + ih * 64 + ty * 4 + i;
#pragma unroll
            for (int jh = 0; jh < 2; jh++) {
                const int col = bn + jh * 64 + tx * 4;
                float4 v;
                v.x = acc[ih * 4 + i][jh * 4 + 0] + bb[jh * 4 + 0];
                v.y = acc[ih * 4 + i][jh * 4 + 1] + bb[jh * 4 + 1];
                v.z = acc[ih * 4 + i][jh * 4 + 2] + bb[jh * 4 + 2];
                v.w = acc[ih * 4 + i][jh * 4 + 3] + bb[jh * 4 + 3];
                *(float4*)&out[(size_t)row * DM + col] = v;
            }
        }
    }
}

// =============================================================================
extern "C" void kernel_launch(void* const* d_in, const int* in_sizes, int n_in,
                              void* d_out, int out_size)
{
    (void)in_sizes; (void)n_in; (void)out_size;
    const float* x  = (const float*)d_in[0];
    const float* Wq = (const float*)d_in[1];
    const float* bq = (const float*)d_in[2];
    const float* Wk = (const float*)d_in[3];
    const float* bk = (const float*)d_in[4];
    const float* Wv = (const float*)d_in[5];
    const float* bv = (const float*)d_in[6];
    const float* Wo = (const float*)d_in[7];
    const float* bo = (const float*)d_in[8];
    float* out = (float*)d_out;

    // 1) QKV projections (128x128 tiles)
    {
        dim3 grid(DM / 128, MROWS / 128, 3);
        k_proj_qkv<<<grid, 256>>>(x, Wq, bq, Wk, bk, Wv, bv);
    }
    // 2) fused flash attention
    {
        const size_t att_smem = (size_t)ATT_SMEM_FLOATS * sizeof(float);
        cudaFuncSetAttribute(k_attn, cudaFuncAttributeMaxDynamicSharedMemorySize,
                             (int)att_smem);
        dim3 grid(SEQ / 64, NBH);
        k_attn<<<grid, 256, att_smem>>>();
    }
    // 3) output projection
    {
        dim3 grid(DM / 128, MROWS / 128, 1);
        k_proj_out<<<grid, 256>>>(Wo, bo, out);
    }
}

// round 4
// speedup vs baseline: 1.6927x; 1.3030x over previous
#include <cuda_runtime.h>
#include <cuda_bf16.h>
#include <math.h>
#include <stdint.h>

#define BATCH 4
#define SEQ   2048
#define DM    1024
#define NH    16
#define HD    64
#define MROWS (BATCH*SEQ)      // 8192
#define NBH   (BATCH*NH)       // 64

// ---------------- scratch (device globals: allocation-free rule) -------------
__device__ float g_q[(size_t)NBH * SEQ * HD];      // [bh, s, 64] fp32
__device__ float g_k[(size_t)NBH * SEQ * HD];
__device__ float g_v[(size_t)NBH * SEQ * HD];
__device__ float g_ctx[(size_t)MROWS * DM];        // [b, s, h*64+d] fp32

__device__ __nv_bfloat16 g_xhi[(size_t)MROWS * DM];
__device__ __nv_bfloat16 g_xlo[(size_t)MROWS * DM];
__device__ __nv_bfloat16 g_chi[(size_t)MROWS * DM];
__device__ __nv_bfloat16 g_clo[(size_t)MROWS * DM];
__device__ __nv_bfloat16 g_wThi[(size_t)4 * DM * DM];  // W^T [n][k], 4 weights
__device__ __nv_bfloat16 g_wTlo[(size_t)4 * DM * DM];

// ======================= mma.sync helpers ====================================
__device__ __forceinline__ void ldm_x4(uint32_t addr, uint32_t* r) {
    asm volatile("ldmatrix.sync.aligned.m8n8.x4.shared.b16 {%0,%1,%2,%3}, [%4];"
                 : "=r"(r[0]), "=r"(r[1]), "=r"(r[2]), "=r"(r[3]) : "r"(addr));
}
__device__ __forceinline__ void mma_bf16(float* c, const uint32_t* a,
                                         uint32_t b0, uint32_t b1) {
    asm volatile(
        "mma.sync.aligned.m16n8k16.row.col.f32.bf16.bf16.f32 "
        "{%0,%1,%2,%3}, {%4,%5,%6,%7}, {%8,%9}, {%0,%1,%2,%3};"
        : "+f"(c[0]), "+f"(c[1]), "+f"(c[2]), "+f"(c[3])
        : "r"(a[0]), "r"(a[1]), "r"(a[2]), "r"(a[3]), "r"(b0), "r"(b1));
}

// =============================================================================
// Kernel: split fp32 -> (hi, lo) bf16.  which=0: x -> g_xhi/g_xlo
//                                       which=1: g_ctx -> g_chi/g_clo
// =============================================================================
__global__ __launch_bounds__(256) void k_split(const float* __restrict__ x, int which)
{
    const float* __restrict__ src = (which == 0) ? x : g_ctx;
    __nv_bfloat16* __restrict__ hi = (which == 0) ? g_xhi : g_chi;
    __nv_bfloat16* __restrict__ lo = (which == 0) ? g_xlo : g_clo;

    const size_t i = ((size_t)blockIdx.x * 256 + threadIdx.x) * 4;
    float4 v = *(const float4*)(src + i);
    float vv[4] = {v.x, v.y, v.z, v.w};
    __nv_bfloat16 h[4], l[4];
#pragma unroll
    for (int u = 0; u < 4; u++) {
        h[u] = __float2bfloat16(vv[u]);
        l[u] = __float2bfloat16(vv[u] - __bfloat162float(h[u]));
    }
    *(uint2*)(hi + i) = *(uint2*)h;
    *(uint2*)(lo + i) = *(uint2*)l;
}

// =============================================================================
// Kernel: transpose + split weights.  W [k][n] fp32 -> WT hi/lo [n][k] bf16.
// =============================================================================
__global__ __launch_bounds__(256) void k_wT(
    const float* __restrict__ Wq, const float* __restrict__ Wk,
    const float* __restrict__ Wv, const float* __restrict__ Wo)
{
    const int z = blockIdx.z;
    const float* __restrict__ W = (z == 0) ? Wq : (z == 1) ? Wk : (z == 2) ? Wv : Wo;
    __nv_bfloat16* __restrict__ Th = g_wThi + (size_t)z * DM * DM;
    __nv_bfloat16* __restrict__ Tl = g_wTlo + (size_t)z * DM * DM;

    __shared__ float t[32][33];
    const int bk = blockIdx.y * 32, bn = blockIdx.x * 32;
    const int tx = threadIdx.x & 31, ty = threadIdx.x >> 5;

#pragma unroll
    for (int i = 0; i < 4; i++)
        t[ty + i * 8][tx] = W[(size_t)(bk + ty + i * 8) * DM + bn + tx];
    __syncthreads();
#pragma unroll
    for (int i = 0; i < 4; i++) {
        const float v = t[tx][ty + i * 8];
        const __nv_bfloat16 h = __float2bfloat16(v);
        const size_t o = (size_t)(bn + ty + i * 8) * DM + bk + tx;
        Th[o] = h;
        Tl[o] = __float2bfloat16(v - __bfloat162float(h));
    }
}

// =============================================================================
// Kernel: mma.sync bf16-split GEMM, 128x128 block, BK=32, 8 warps @ 32x64.
// D = Ahi@Bhi + Alo@Bhi + Ahi@Blo  (fp32 accum).
// mode = modeBase + blockIdx.z: 0/1/2 -> g_q/g_k/g_v permuted; 3 -> finalOut.
// =============================================================================
#define PITCH 40   // bf16 elems per smem row (32 data + 8 pad): 80B, 16B-aligned

__global__ __launch_bounds__(256) void k_gemm(
    const float* __restrict__ b0, const float* __restrict__ b1,
    const float* __restrict__ b2, float* __restrict__ finalOut, int modeBase)
{
    __shared__ __nv_bfloat16 sAhi[128 * PITCH];
    __shared__ __nv_bfloat16 sAlo[128 * PITCH];
    __shared__ __nv_bfloat16 sBhi[128 * PITCH];
    __shared__ __nv_bfloat16 sBlo[128 * PITCH];

    const int z = blockIdx.z;
    const int mode = modeBase + z;
    const __nv_bfloat16* __restrict__ Ahi = (mode < 3) ? g_xhi : g_chi;
    const __nv_bfloat16* __restrict__ Alo = (mode < 3) ? g_xlo : g_clo;
    const int wsel = (mode < 3) ? z : 3;
    const __nv_bfloat16* __restrict__ Bhi = g_wThi + (size_t)wsel * DM * DM;
    const __nv_bfloat16* __restrict__ Blo = g_wTlo + (size_t)wsel * DM * DM;
    const float* __restrict__ bias = (mode == 0) ? b0 : (mode == 1) ? b1
                                    : (mode == 2) ? b2 : b0;

    const int bm = blockIdx.y * 128;
    const int bn = blockIdx.x * 128;
    const int tid = threadIdx.x;
    const int wid = tid >> 5;
    const int lane = tid & 31;
    const int wy = wid >> 1;   // 0..3  (m)
    const int wx = wid & 1;    // 0..1  (n)

    const uint32_t aAhi = (uint32_t)__cvta_generic_to_shared(sAhi);
    const uint32_t aAlo = (uint32_t)__cvta_generic_to_shared(sAlo);
    const uint32_t aBhi = (uint32_t)__cvta_generic_to_shared(sBhi);
    const uint32_t aBlo = (uint32_t)__cvta_generic_to_shared(sBlo);

    // per-lane ldmatrix element offset within a 16x16 tile region
    const uint32_t lmo = (uint32_t)((lane & 15) * PITCH + (lane >> 4) * 8);

    float acc[2][8][4];
#pragma unroll
    for (int a = 0; a < 2; a++)
#pragma unroll
        for (int b = 0; b < 8; b++)
#pragma unroll
            for (int c = 0; c < 4; c++) acc[a][b][c] = 0.f;

    // cooperative loader indices: 512 uint4 per matrix per ktile, 2/thread
    // idx -> row = idx>>2, seg = idx&3 (8 bf16 each)
    for (int kc = 0; kc < 32; kc++) {
        const int k0 = kc * 32;
#pragma unroll
        for (int it = 0; it < 2; it++) {
            const int idx = it * 256 + tid;
            const int r   = idx >> 2;
            const int sg  = (idx & 3) * 8;
            const size_t gA = (size_t)(bm + r) * DM + k0 + sg;
            const size_t gB = (size_t)(bn + r) * DM + k0 + sg;
            const int so = r * PITCH + sg;
            *(uint4*)&sAhi[so] = *(const uint4*)(Ahi + gA);
            *(uint4*)&sAlo[so] = *(const uint4*)(Alo + gA);
            *(uint4*)&sBhi[so] = *(const uint4*)(Bhi + gB);
            *(uint4*)&sBlo[so] = *(const uint4*)(Blo + gB);
        }
        __syncthreads();

#pragma unroll
        for (int ks = 0; ks < 2; ks++) {
            uint32_t ahi[2][4], alo[2][4], bhi[4][4], blo[4][4];
#pragma unroll
            for (int mt = 0; mt < 2; mt++) {
                const uint32_t org = (uint32_t)((wy * 32 + mt * 16) * PITCH + ks * 16);
                ldm_x4(aAhi + (org + lmo) * 2, ahi[mt]);
                ldm_x4(aAlo + (org + lmo) * 2, alo[mt]);
            }
#pragma unroll
            for (int np = 0; np < 4; np++) {
                const uint32_t org = (uint32_t)((wx * 64 + np * 16) * PITCH + ks * 16);
                ldm_x4(aBhi + (org + lmo) * 2, bhi[np]);
                ldm_x4(aBlo + (org + lmo) * 2, blo[np]);
            }
#pragma unroll
            for (int mt = 0; mt < 2; mt++) {
#pragma unroll
                for (int np = 0; np < 4; np++) {
                    mma_bf16(acc[mt][np * 2 + 0], ahi[mt], bhi[np][0], bhi[np][2]);
                    mma_bf16(acc[mt][np * 2 + 1], ahi[mt], bhi[np][1], bhi[np][3]);
                    mma_bf16(acc[mt][np * 2 + 0], alo[mt], bhi[np][0], bhi[np][2]);
                    mma_bf16(acc[mt][np * 2 + 1], alo[mt], bhi[np][1], bhi[np][3]);
                    mma_bf16(acc[mt][np * 2 + 0], ahi[mt], blo[np][0], blo[np][2]);
                    mma_bf16(acc[mt][np * 2 + 1], ahi[mt], blo[np][1], blo[np][3]);
                }
            }
        }
        __syncthreads();
    }

    // epilogue
    const int g   = lane >> 2;
    const int tig = lane & 3;
#pragma unroll
    for (int mt = 0; mt < 2; mt++) {
        const int row0 = bm + wy * 32 + mt * 16 + g;
#pragma unroll
        for (int nf = 0; nf < 8; nf++) {
            const int col = bn + wx * 64 + nf * 8 + tig * 2;
            const float* ac = acc[mt][nf];
            const float bx = bias[col], by = bias[col + 1];
            if (mode < 3) {
                float* __restrict__ outp = (mode == 0) ? g_q : (mode == 1) ? g_k : g_v;
                const int h = col >> 6, dh = col & 63;
#pragma unroll
                for (int rr = 0; rr < 2; rr++) {
                    const int row = row0 + rr * 8;
                    const int b = row >> 11, s = row & 2047;
                    float2 v = make_float2(ac[rr * 2 + 0] + bx, ac[rr * 2 + 1] + by);
                    *(float2*)&outp[(((size_t)(b * NH + h)) * SEQ + s) * HD + dh] = v;
                }
            } else {
#pragma unroll
                for (int rr = 0; rr < 2; rr++) {
                    const int row = row0 + rr * 8;
                    float2 v = make_float2(ac[rr * 2 + 0] + bx, ac[rr * 2 + 1] + by);
                    *(float2*)&finalOut[(size_t)row * DM + col] = v;
                }
            }
        }
    }
}

// =============================================================================
// Kernel: fused flash attention (fp32 SIMT, unchanged from R2).
// =============================================================================
#define ST_PITCH 68
#define ATT_SMEM_FLOATS (64*64 + 64*ST_PITCH + 64*64 + 4*64 + 3*64)

__global__ __launch_bounds__(256) void k_attn()
{
    extern __shared__ float smf[];
    float* Qt   = smf;
    float* KtSt = smf + 64 * 64;
    float* Vs   = KtSt + 64 * ST_PITCH;
    float* red  = Vs + 64 * 64;
    float* mrow = red + 4 * 64;
    float* lrow = mrow + 64;
    float* srow = lrow + 64;

    const int bh = blockIdx.y;
    const int qb = (int)gridDim.x - 1 - (int)blockIdx.x;
    const int tid = threadIdx.x;
    const int ty = tid >> 4, tx = tid & 15;

    const float* __restrict__ Qg = g_q + (size_t)bh * SEQ * HD;
    const float* __restrict__ Kg = g_k + (size_t)bh * SEQ * HD;
    const float* __restrict__ Vg = g_v + (size_t)bh * SEQ * HD;

    {
        const int m  = tid >> 2;
        const int d0 = (tid & 3) * 16;
        const float* src = Qg + (size_t)(qb * 64 + m) * HD + d0;
#pragma unroll
        for (int u = 0; u < 4; u++) {
            float4 v = *(const float4*)(src + u * 4);
            Qt[(d0 + u * 4 + 0) * 64 + m] = v.x;
            Qt[(d0 + u * 4 + 1) * 64 + m] = v.y;
            Qt[(d0 + u * 4 + 2) * 64 + m] = v.z;
            Qt[(d0 + u * 4 + 3) * 64 + m] = v.w;
        }
    }
    if (tid < 64) { mrow[tid] = -INFINITY; lrow[tid] = 0.f; }

    float o[4][4];
#pragma unroll
    for (int i = 0; i < 4; i++)
#pragma unroll
        for (int j = 0; j < 4; j++) o[i][j] = 0.f;

    const int c  = tid >> 6;
    const int ms = tid & 63;

    for (int kb = 0; kb <= qb; kb++) {
        __syncthreads();
        {
            const int n  = tid >> 2;
            const int d0 = (tid & 3) * 16;
            const float* ks = Kg + (size_t)(kb * 64 + n) * HD + d0;
            const float* vp = Vg + (size_t)(kb * 64 + n) * HD + d0;
#pragma unroll
            for (int u = 0; u < 4; u++) {
                float4 kv = *(const float4*)(ks + u * 4);
                KtSt[(d0 + u * 4 + 0) * ST_PITCH + n] = kv.x;
                KtSt[(d0 + u * 4 + 1) * ST_PITCH + n] = kv.y;
                KtSt[(d0 + u * 4 + 2) * ST_PITCH + n] = kv.z;
                KtSt[(d0 + u * 4 + 3) * ST_PITCH + n] = kv.w;
                *(float4*)&Vs[n * 64 + d0 + u * 4] = *(const float4*)(vp + u * 4);
            }
        }
        __syncthreads();

        float s[4][4];
#pragma unroll
        for (int i = 0; i < 4; i++)
#pragma unroll
            for (int j = 0; j < 4; j++) s[i][j] = 0.f;
#pragma unroll 8
        for (int kk = 0; kk < 64; kk++) {
            float4 a = *(const float4*)&Qt[kk * 64 + ty * 4];
            float4 b = *(const float4*)&KtSt[kk * ST_PITCH + tx * 4];
            float av[4] = {a.x, a.y, a.z, a.w};
            float bv4[4] = {b.x, b.y, b.z, b.w};
#pragma unroll
            for (int i = 0; i < 4; i++)
#pragma unroll
                for (int j = 0; j < 4; j++) s[i][j] = fmaf(av[i], bv4[j], s[i][j]);
        }
        __syncthreads();

        const float SC = 1.0f / 32.0f;
        const bool diag = (kb == qb);
#pragma unroll
        for (int i = 0; i < 4; i++) {
#pragma unroll
            for (int j = 0; j < 4; j++) {
                float v = s[i][j] * SC;
                if (diag && (tx * 4 + j) > (ty * 4 + i)) v = -INFINITY;
                KtSt[(tx * 4 + j) * ST_PITCH + ty * 4 + i] = v;
            }
        }
        __syncthreads();

        float pm = -INFINITY;
#pragma unroll
        for (int u = 0; u < 16; u++)
            pm = fmaxf(pm, KtSt[(c * 16 + u) * ST_PITCH + ms]);
        red[c * 64 + ms] = pm;
        __syncthreads();
        if (c == 0) {
            float t = fmaxf(fmaxf(red[ms], red[64 + ms]), fmaxf(red[128 + ms], red[192 + ms]));
            float mo = mrow[ms];
            float mn = fmaxf(mo, t);
            srow[ms] = __expf(mo - mn);
            mrow[ms] = mn;
        }
        __syncthreads();
        const float mn = mrow[ms];
        float ps = 0.f;
#pragma unroll
        for (int u = 0; u < 16; u++) {
            const int idx = (c * 16 + u) * ST_PITCH + ms;
            float p = __expf(KtSt[idx] - mn);
            KtSt[idx] = p;
            ps += p;
        }
        red[c * 64 + ms] = ps;
        __syncthreads();
        if (c == 0)
            lrow[ms] = lrow[ms] * srow[ms] + (red[ms] + red[64 + ms] + red[128 + ms] + red[192 + ms]);
        __syncthreads();

        float sc[4];
#pragma unroll
        for (int i = 0; i < 4; i++) sc[i] = srow[ty * 4 + i];
#pragma unroll
        for (int i = 0; i < 4; i++)
#pragma unroll
            for (int j = 0; j < 4; j++) o[i][j] *= sc[i];
#pragma unroll 8
        for (int n = 0; n < 64; n++) {
            float4 a = *(const float4*)&KtSt[n * ST_PITCH + ty * 4];
            float4 b = *(const float4*)&Vs[n * 64 + tx * 4];
            float av[4] = {a.x, a.y, a.z, a.w};
            float bv4[4] = {b.x, b.y, b.z, b.w};
#pragma unroll
            for (int i = 0; i < 4; i++)
#pragma unroll
                for (int j = 0; j < 4; j++) o[i][j] = fmaf(av[i], bv4[j], o[i][j]);
        }
    }
    __syncthreads();

    const int b = bh >> 4, h = bh & 15;
#pragma unroll
    for (int i = 0; i < 4; i++) {
        const float inv = 1.0f / lrow[ty * 4 + i];
        const int srw = qb * 64 + ty * 4 + i;
        float4 v;
        v.x = o[i][0] * inv; v.y = o[i][1] * inv;
        v.z = o[i][2] * inv; v.w = o[i][3] * inv;
        *(float4*)&g_ctx[((size_t)(b * SEQ + srw)) * DM + h * HD + tx * 4] = v;
    }
}

// =============================================================================
extern "C" void kernel_launch(void* const* d_in, const int* in_sizes, int n_in,
                              void* d_out, int out_size)
{
    (void)in_sizes; (void)n_in; (void)out_size;
    const float* x  = (const float*)d_in[0];
    const float* Wq = (const float*)d_in[1];
    const float* bq = (const float*)d_in[2];
    const float* Wk = (const float*)d_in[3];
    const float* bk = (const float*)d_in[4];
    const float* Wv = (const float*)d_in[5];
    const float* bv = (const float*)d_in[6];
    const float* Wo = (const float*)d_in[7];
    const float* bo = (const float*)d_in[8];
    float* out = (float*)d_out;

    cudaFuncSetAttribute(k_attn, cudaFuncAttributeMaxDynamicSharedMemorySize,
                         (int)(ATT_SMEM_FLOATS * sizeof(float)));

    // 1) weight transpose + split, input split
    k_wT<<<dim3(32, 32, 4), 256>>>(Wq, Wk, Wv, Wo);
    k_split<<<(MROWS * DM) / 1024, 256>>>(x, 0);

    // 2) QKV projections on tensor cores (mma.sync)
    k_gemm<<<dim3(DM / 128, MROWS / 128, 3), 256>>>(bq, bk, bv, nullptr, 0);

    // 3) fused flash attention (fp32 SIMT)
    k_attn<<<dim3(SEQ / 64, NBH), 256, ATT_SMEM_FLOATS * sizeof(float)>>>();

    // 4) ctx split + output projection on tensor cores
    k_split<<<(MROWS * DM) / 1024, 256>>>(nullptr, 1);
    k_gemm<<<dim3(DM / 128, MROWS / 128, 1), 256>>>(bo, bo, bo, out, 3);
}

// round 5
// speedup vs baseline: 3.0328x; 1.7917x over previous
#include <cuda_runtime.h>
#include <cuda_bf16.h>
#include <math.h>
#include <stdint.h>

#define BATCH 4
#define SEQ   2048
#define DM    1024
#define NH    16
#define HD    64
#define MROWS (BATCH*SEQ)      // 8192
#define NBH   (BATCH*NH)       // 64

// ---------------- scratch (device globals: allocation-free rule) -------------
__device__ __nv_bfloat16 g_xhi[(size_t)MROWS * DM];
__device__ __nv_bfloat16 g_xlo[(size_t)MROWS * DM];
__device__ __nv_bfloat16 g_chi[(size_t)MROWS * DM];     // ctx split
__device__ __nv_bfloat16 g_clo[(size_t)MROWS * DM];
__device__ __nv_bfloat16 g_wThi[(size_t)4 * DM * DM];   // W^T [n][k]
__device__ __nv_bfloat16 g_wTlo[(size_t)4 * DM * DM];
__device__ __nv_bfloat16 g_qhi[(size_t)NBH * SEQ * HD]; // [bh][s][64]
__device__ __nv_bfloat16 g_qlo[(size_t)NBH * SEQ * HD];
__device__ __nv_bfloat16 g_khi[(size_t)NBH * SEQ * HD];
__device__ __nv_bfloat16 g_klo[(size_t)NBH * SEQ * HD];
__device__ __nv_bfloat16 g_vhi[(size_t)NBH * SEQ * HD];
__device__ __nv_bfloat16 g_vlo[(size_t)NBH * SEQ * HD];

// ======================= mma.sync helpers ====================================
__device__ __forceinline__ void ldm_x4(uint32_t addr, uint32_t* r) {
    asm volatile("ldmatrix.sync.aligned.m8n8.x4.shared.b16 {%0,%1,%2,%3}, [%4];"
                 : "=r"(r[0]), "=r"(r[1]), "=r"(r[2]), "=r"(r[3]) : "r"(addr));
}
__device__ __forceinline__ void ldm_x4_t(uint32_t addr, uint32_t* r) {
    asm volatile("ldmatrix.sync.aligned.m8n8.x4.trans.shared.b16 {%0,%1,%2,%3}, [%4];"
                 : "=r"(r[0]), "=r"(r[1]), "=r"(r[2]), "=r"(r[3]) : "r"(addr));
}
__device__ __forceinline__ void mma_bf16(float* c, const uint32_t* a,
                                         uint32_t b0, uint32_t b1) {
    asm volatile(
        "mma.sync.aligned.m16n8k16.row.col.f32.bf16.bf16.f32 "
        "{%0,%1,%2,%3}, {%4,%5,%6,%7}, {%8,%9}, {%0,%1,%2,%3};"
        : "+f"(c[0]), "+f"(c[1]), "+f"(c[2]), "+f"(c[3])
        : "r"(a[0]), "r"(a[1]), "r"(a[2]), "r"(a[3]), "r"(b0), "r"(b1));
}
__device__ __forceinline__ uint32_t pkbf(float x, float y) {
    __nv_bfloat162 t = __floats2bfloat162_rn(x, y);
    return *(uint32_t*)&t;
}

// =============================================================================
// split fp32 x -> hi/lo bf16
// =============================================================================
__global__ __launch_bounds__(256) void k_split(const float* __restrict__ x)
{
    const size_t i = ((size_t)blockIdx.x * 256 + threadIdx.x) * 4;
    float4 v = *(const float4*)(x + i);
    float vv[4] = {v.x, v.y, v.z, v.w};
    __nv_bfloat16 h[4], l[4];
#pragma unroll
    for (int u = 0; u < 4; u++) {
        h[u] = __float2bfloat16(vv[u]);
        l[u] = __float2bfloat16(vv[u] - __bfloat162float(h[u]));
    }
    *(uint2*)(g_xhi + i) = *(uint2*)h;
    *(uint2*)(g_xlo + i) = *(uint2*)l;
}

// =============================================================================
// transpose + split weights: W [k][n] fp32 -> WT hi/lo [n][k] bf16
// =============================================================================
__global__ __launch_bounds__(256) void k_wT(
    const float* __restrict__ Wq, const float* __restrict__ Wk,
    const float* __restrict__ Wv, const float* __restrict__ Wo)
{
    const int z = blockIdx.z;
    const float* __restrict__ W = (z == 0) ? Wq : (z == 1) ? Wk : (z == 2) ? Wv : Wo;
    __nv_bfloat16* __restrict__ Th = g_wThi + (size_t)z * DM * DM;
    __nv_bfloat16* __restrict__ Tl = g_wTlo + (size_t)z * DM * DM;

    __shared__ float t[32][33];
    const int bk = blockIdx.y * 32, bn = blockIdx.x * 32;
    const int tx = threadIdx.x & 31, ty = threadIdx.x >> 5;

#pragma unroll
    for (int i = 0; i < 4; i++)
        t[ty + i * 8][tx] = W[(size_t)(bk + ty + i * 8) * DM + bn + tx];
    __syncthreads();
#pragma unroll
    for (int i = 0; i < 4; i++) {
        const float v = t[tx][ty + i * 8];
        const __nv_bfloat16 h = __float2bfloat16(v);
        const size_t o = (size_t)(bn + ty + i * 8) * DM + bk + tx;
        Th[o] = h;
        Tl[o] = __float2bfloat16(v - __bfloat162float(h));
    }
}

// =============================================================================
// mma.sync bf16-split GEMM, 128x128 block, BK=32, 8 warps @ 32x64.
// mode<3: write q/k/v split bf16 permuted [bh][s][64].  mode 3: fp32 out.
// =============================================================================
#define PITCH 40

__global__ __launch_bounds__(256) void k_gemm(
    const float* __restrict__ b0p, const float* __restrict__ b1p,
    const float* __restrict__ b2p, float* __restrict__ finalOut, int modeBase)
{
    __shared__ __nv_bfloat16 sAhi[128 * PITCH];
    __shared__ __nv_bfloat16 sAlo[128 * PITCH];
    __shared__ __nv_bfloat16 sBhi[128 * PITCH];
    __shared__ __nv_bfloat16 sBlo[128 * PITCH];

    const int z = blockIdx.z;
    const int mode = modeBase + z;
    const __nv_bfloat16* __restrict__ Ahi = (mode < 3) ? g_xhi : g_chi;
    const __nv_bfloat16* __restrict__ Alo = (mode < 3) ? g_xlo : g_clo;
    const int wsel = (mode < 3) ? z : 3;
    const __nv_bfloat16* __restrict__ Bhi = g_wThi + (size_t)wsel * DM * DM;
    const __nv_bfloat16* __restrict__ Blo = g_wTlo + (size_t)wsel * DM * DM;
    const float* __restrict__ bias = (mode == 0) ? b0p : (mode == 1) ? b1p
                                    : (mode == 2) ? b2p : b0p;

    const int bm = blockIdx.y * 128;
    const int bn = blockIdx.x * 128;
    const int tid = threadIdx.x;
    const int wid = tid >> 5;
    const int lane = tid & 31;
    const int wy = wid >> 1;
    const int wx = wid & 1;

    const uint32_t aAhi = (uint32_t)__cvta_generic_to_shared(sAhi);
    const uint32_t aAlo = (uint32_t)__cvta_generic_to_shared(sAlo);
    const uint32_t aBhi = (uint32_t)__cvta_generic_to_shared(sBhi);
    const uint32_t aBlo = (uint32_t)__cvta_generic_to_shared(sBlo);

    const uint32_t lmo = (uint32_t)((lane & 15) * PITCH + (lane >> 4) * 8);

    float acc[2][8][4];
#pragma unroll
    for (int a = 0; a < 2; a++)
#pragma unroll
        for (int b = 0; b < 8; b++)
#pragma unroll
            for (int c = 0; c < 4; c++) acc[a][b][c] = 0.f;

    for (int kc = 0; kc < 32; kc++) {
        const int k0 = kc * 32;
#pragma unroll
        for (int it = 0; it < 2; it++) {
            const int idx = it * 256 + tid;
            const int r   = idx >> 2;
            const int sg  = (idx & 3) * 8;
            const size_t gA = (size_t)(bm + r) * DM + k0 + sg;
            const size_t gB = (size_t)(bn + r) * DM + k0 + sg;
            const int so = r * PITCH + sg;
            *(uint4*)&sAhi[so] = *(const uint4*)(Ahi + gA);
            *(uint4*)&sAlo[so] = *(const uint4*)(Alo + gA);
            *(uint4*)&sBhi[so] = *(const uint4*)(Bhi + gB);
            *(uint4*)&sBlo[so] = *(const uint4*)(Blo + gB);
        }
        __syncthreads();

#pragma unroll
        for (int ks = 0; ks < 2; ks++) {
            uint32_t ahi[2][4], alo[2][4], bhi[4][4], blo[4][4];
#pragma unroll
            for (int mt = 0; mt < 2; mt++) {
                const uint32_t org = (uint32_t)((wy * 32 + mt * 16) * PITCH + ks * 16);
                ldm_x4(aAhi + (org + lmo) * 2, ahi[mt]);
                ldm_x4(aAlo + (org + lmo) * 2, alo[mt]);
            }
#pragma unroll
            for (int np = 0; np < 4; np++) {
                const uint32_t org = (uint32_t)((wx * 64 + np * 16) * PITCH + ks * 16);
                ldm_x4(aBhi + (org + lmo) * 2, bhi[np]);
                ldm_x4(aBlo + (org + lmo) * 2, blo[np]);
            }
#pragma unroll
            for (int mt = 0; mt < 2; mt++) {
#pragma unroll
                for (int np = 0; np < 4; np++) {
                    mma_bf16(acc[mt][np * 2 + 0], ahi[mt], bhi[np][0], bhi[np][2]);
                    mma_bf16(acc[mt][np * 2 + 1], ahi[mt], bhi[np][1], bhi[np][3]);
                    mma_bf16(acc[mt][np * 2 + 0], alo[mt], bhi[np][0], bhi[np][2]);
                    mma_bf16(acc[mt][np * 2 + 1], alo[mt], bhi[np][1], bhi[np][3]);
                    mma_bf16(acc[mt][np * 2 + 0], ahi[mt], blo[np][0], blo[np][2]);
                    mma_bf16(acc[mt][np * 2 + 1], ahi[mt], blo[np][1], blo[np][3]);
                }
            }
        }
        __syncthreads();
    }

    // epilogue
    const int g   = lane >> 2;
    const int tig = lane & 3;
#pragma unroll
    for (int mt = 0; mt < 2; mt++) {
        const int row0 = bm + wy * 32 + mt * 16 + g;
#pragma unroll
        for (int nf = 0; nf < 8; nf++) {
            const int col = bn + wx * 64 + nf * 8 + tig * 2;
            const float* ac = acc[mt][nf];
            const float bx = bias[col], by = bias[col + 1];
            if (mode < 3) {
                __nv_bfloat16* __restrict__ ohi = (mode == 0) ? g_qhi : (mode == 1) ? g_khi : g_vhi;
                __nv_bfloat16* __restrict__ olo = (mode == 0) ? g_qlo : (mode == 1) ? g_klo : g_vlo;
                const int h = col >> 6, dh = col & 63;
#pragma unroll
                for (int rr = 0; rr < 2; rr++) {
                    const int row = row0 + rr * 8;
                    const int b = row >> 11, s = row & 2047;
                    const float vx = ac[rr * 2 + 0] + bx;
                    const float vy = ac[rr * 2 + 1] + by;
                    const uint32_t ph = pkbf(vx, vy);
                    const float hx = __bfloat162float(__float2bfloat16(vx));
                    const float hy = __bfloat162float(__float2bfloat16(vy));
                    const uint32_t pl = pkbf(vx - hx, vy - hy);
                    const size_t o = (((size_t)(b * NH + h)) * SEQ + s) * HD + dh;
                    *(uint32_t*)&ohi[o] = ph;
                    *(uint32_t*)&olo[o] = pl;
                }
            } else {
#pragma unroll
                for (int rr = 0; rr < 2; rr++) {
                    const int row = row0 + rr * 8;
                    float2 v = make_float2(ac[rr * 2 + 0] + bx, ac[rr * 2 + 1] + by);
                    *(float2*)&finalOut[(size_t)row * DM + col] = v;
                }
            }
        }
    }
}

// =============================================================================
// Flash attention on mma.sync, split bf16, Q-tile 128 x KV-tile 64.
// 8 warps, warp w owns Q rows [qt*128 + w*16, +16).  Writes ctx split bf16.
// =============================================================================
#define APITCH 72
#define ATT_SMEM_BYTES ((128*2 + 64*4) * APITCH * 2)   // 73728

__global__ __launch_bounds__(256) void k_attn()
{
    extern __shared__ __nv_bfloat16 smb[];
    __nv_bfloat16* sQhi = smb;
    __nv_bfloat16* sQlo = sQhi + 128 * APITCH;
    __nv_bfloat16* sKhi = sQlo + 128 * APITCH;
    __nv_bfloat16* sKlo = sKhi + 64 * APITCH;
    __nv_bfloat16* sVhi = sKlo + 64 * APITCH;
    __nv_bfloat16* sVlo = sVhi + 64 * APITCH;

    const int bh  = blockIdx.y;
    const int qt  = (int)gridDim.x - 1 - (int)blockIdx.x;  // heavy first
    const int tid = threadIdx.x;
    const int wid = tid >> 5;
    const int lane = tid & 31;
    const int g   = lane >> 2;
    const int q2  = lane & 3;

    const __nv_bfloat16* __restrict__ Qhi = g_qhi + (size_t)bh * SEQ * HD;
    const __nv_bfloat16* __restrict__ Qlo = g_qlo + (size_t)bh * SEQ * HD;
    const __nv_bfloat16* __restrict__ Khi = g_khi + (size_t)bh * SEQ * HD;
    const __nv_bfloat16* __restrict__ Klo = g_klo + (size_t)bh * SEQ * HD;
    const __nv_bfloat16* __restrict__ Vhi = g_vhi + (size_t)bh * SEQ * HD;
    const __nv_bfloat16* __restrict__ Vlo = g_vlo + (size_t)bh * SEQ * HD;

    // load Q tile (128 x 64): 1024 uint4 per matrix, 4 per thread
#pragma unroll
    for (int it = 0; it < 4; it++) {
        const int idx = it * 256 + tid;
        const int r  = idx >> 3;
        const int c8 = (idx & 7) * 8;
        const size_t gsrc = (size_t)(qt * 128 + r) * HD + c8;
        *(uint4*)&sQhi[r * APITCH + c8] = *(const uint4*)(Qhi + gsrc);
        *(uint4*)&sQlo[r * APITCH + c8] = *(const uint4*)(Qlo + gsrc);
    }

    const uint32_t aQhi = (uint32_t)__cvta_generic_to_shared(sQhi);
    const uint32_t aQlo = (uint32_t)__cvta_generic_to_shared(sQlo);
    const uint32_t aKhi = (uint32_t)__cvta_generic_to_shared(sKhi);
    const uint32_t aKlo = (uint32_t)__cvta_generic_to_shared(sKlo);
    const uint32_t aVhi = (uint32_t)__cvta_generic_to_shared(sVhi);
    const uint32_t aVlo = (uint32_t)__cvta_generic_to_shared(sVlo);
    const uint32_t lmo = (uint32_t)((lane & 15) * APITCH + (lane >> 4) * 8);

    float o[8][4];
#pragma unroll
    for (int j = 0; j < 8; j++)
#pragma unroll
        for (int c = 0; c < 4; c++) o[j][c] = 0.f;
    float m0 = -INFINITY, m1 = -INFINITY, l0 = 0.f, l1 = 0.f;

    const int row0 = qt * 128 + wid * 16 + g;
    const int row1 = row0 + 8;
    const float SC = 1.0f / 32.0f;
    const int nkb = 2 * qt + 2;

    for (int kb = 0; kb < nkb; kb++) {
        __syncthreads();   // prior iter's smem reads done
        // load K/V tiles (64 x 64): 512 uint4 per matrix, 2 per thread
#pragma unroll
        for (int it = 0; it < 2; it++) {
            const int idx = it * 256 + tid;
            const int r  = idx >> 3;
            const int c8 = (idx & 7) * 8;
            const size_t gsrc = (size_t)(kb * 64 + r) * HD + c8;
            const int so = r * APITCH + c8;
            *(uint4*)&sKhi[so] = *(const uint4*)(Khi + gsrc);
            *(uint4*)&sKlo[so] = *(const uint4*)(Klo + gsrc);
            *(uint4*)&sVhi[so] = *(const uint4*)(Vhi + gsrc);
            *(uint4*)&sVlo[so] = *(const uint4*)(Vlo + gsrc);
        }
        __syncthreads();

        // ---- S = Q K^T (3-pass split) ----
        float sf[8][4];
#pragma unroll
        for (int j = 0; j < 8; j++)
#pragma unroll
            for (int c = 0; c < 4; c++) sf[j][c] = 0.f;

#pragma unroll
        for (int kc = 0; kc < 4; kc++) {
            uint32_t qh[4], ql[4];
            const uint32_t orgA = (uint32_t)((wid * 16) * APITCH + kc * 16);
            ldm_x4(aQhi + (orgA + lmo) * 2, qh);
            ldm_x4(aQlo + (orgA + lmo) * 2, ql);
#pragma unroll
            for (int np = 0; np < 4; np++) {
                uint32_t kh[4], kl[4];
                const uint32_t orgB = (uint32_t)((np * 16) * APITCH + kc * 16);
                ldm_x4(aKhi + (orgB + lmo) * 2, kh);
                ldm_x4(aKlo + (orgB + lmo) * 2, kl);
                mma_bf16(sf[np * 2 + 0], qh, kh[0], kh[2]);
                mma_bf16(sf[np * 2 + 1], qh, kh[1], kh[3]);
                mma_bf16(sf[np * 2 + 0], ql, kh[0], kh[2]);
                mma_bf16(sf[np * 2 + 1], ql, kh[1], kh[3]);
                mma_bf16(sf[np * 2 + 0], qh, kl[0], kl[2]);
                mma_bf16(sf[np * 2 + 1], qh, kl[1], kl[3]);
            }
        }

        // ---- scale + causal mask ----
#pragma unroll
        for (int j = 0; j < 8; j++) {
            const int col = kb * 64 + j * 8 + q2 * 2;
            sf[j][0] = (col     > row0) ? -INFINITY : sf[j][0] * SC;
            sf[j][1] = (col + 1 > row0) ? -INFINITY : sf[j][1] * SC;
            sf[j][2] = (col     > row1) ? -INFINITY : sf[j][2] * SC;
            sf[j][3] = (col + 1 > row1) ? -INFINITY : sf[j][3] * SC;
        }

        // ---- online softmax ----
        float mx0 = -INFINITY, mx1 = -INFINITY;
#pragma unroll
        for (int j = 0; j < 8; j++) {
            mx0 = fmaxf(mx0, fmaxf(sf[j][0], sf[j][1]));
            mx1 = fmaxf(mx1, fmaxf(sf[j][2], sf[j][3]));
        }
        mx0 = fmaxf(mx0, __shfl_xor_sync(0xffffffff, mx0, 1));
        mx0 = fmaxf(mx0, __shfl_xor_sync(0xffffffff, mx0, 2));
        mx1 = fmaxf(mx1, __shfl_xor_sync(0xffffffff, mx1, 1));
        mx1 = fmaxf(mx1, __shfl_xor_sync(0xffffffff, mx1, 2));
        const float mn0 = fmaxf(m0, mx0);
        const float mn1 = fmaxf(m1, mx1);
        const float esc0 = __expf(m0 - mn0);
        const float esc1 = __expf(m1 - mn1);
        m0 = mn0; m1 = mn1;

        float sum0 = 0.f, sum1 = 0.f;
#pragma unroll
        for (int j = 0; j < 8; j++) {
            sf[j][0] = __expf(sf[j][0] - mn0);
            sf[j][1] = __expf(sf[j][1] - mn0);
            sf[j][2] = __expf(sf[j][2] - mn1);
            sf[j][3] = __expf(sf[j][3] - mn1);
            sum0 += sf[j][0] + sf[j][1];
            sum1 += sf[j][2] + sf[j][3];
        }
        sum0 += __shfl_xor_sync(0xffffffff, sum0, 1);
        sum0 += __shfl_xor_sync(0xffffffff, sum0, 2);
        sum1 += __shfl_xor_sync(0xffffffff, sum1, 1);
        sum1 += __shfl_xor_sync(0xffffffff, sum1, 2);
        l0 = l0 * esc0 + sum0;
        l1 = l1 * esc1 + sum1;

        // rescale O
#pragma unroll
        for (int j = 0; j < 8; j++) {
            o[j][0] *= esc0; o[j][1] *= esc0;
            o[j][2] *= esc1; o[j][3] *= esc1;
        }

        // pack P -> split bf16 A fragments (4 k16 chunks)
        uint32_t pah[4][4], pal[4][4];
#pragma unroll
        for (int kc = 0; kc < 4; kc++) {
            const int j0 = kc * 2, j1 = kc * 2 + 1;
            float f0 = sf[j0][0], f1 = sf[j0][1], f2 = sf[j0][2], f3 = sf[j0][3];
            float g0 = sf[j1][0], g1 = sf[j1][1], g2 = sf[j1][2], g3 = sf[j1][3];
            pah[kc][0] = pkbf(f0, f1);
            pah[kc][1] = pkbf(f2, f3);
            pah[kc][2] = pkbf(g0, g1);
            pah[kc][3] = pkbf(g2, g3);
            pal[kc][0] = pkbf(f0 - __bfloat162float(__float2bfloat16(f0)),
                              f1 - __bfloat162float(__float2bfloat16(f1)));
            pal[kc][1] = pkbf(f2 - __bfloat162float(__float2bfloat16(f2)),
                              f3 - __bfloat162float(__float2bfloat16(f3)));
            pal[kc][2] = pkbf(g0 - __bfloat162float(__float2bfloat16(g0)),
                              g1 - __bfloat162float(__float2bfloat16(g1)));
            pal[kc][3] = pkbf(g2 - __bfloat162float(__float2bfloat16(g2)),
                              g3 - __bfloat162float(__float2bfloat16(g3)));
        }

        // ---- O += P V (3-pass split), V frags via ldmatrix.trans ----
#pragma unroll
        for (int kc = 0; kc < 4; kc++) {
#pragma unroll
            for (int np = 0; np < 4; np++) {
                uint32_t vh[4], vl[4];
                const uint32_t org = (uint32_t)((kc * 16) * APITCH + np * 16);
                ldm_x4_t(aVhi + (org + lmo) * 2, vh);
                ldm_x4_t(aVlo + (org + lmo) * 2, vl);
                mma_bf16(o[np * 2 + 0], pah[kc], vh[0], vh[1]);
                mma_bf16(o[np * 2 + 1], pah[kc], vh[2], vh[3]);
                mma_bf16(o[np * 2 + 0], pal[kc], vh[0], vh[1]);
                mma_bf16(o[np * 2 + 1], pal[kc], vh[2], vh[3]);
                mma_bf16(o[np * 2 + 0], pah[kc], vl[0], vl[1]);
                mma_bf16(o[np * 2 + 1], pah[kc], vl[2], vl[3]);
            }
        }
    }

    // ---- epilogue: normalize + write ctx split bf16 [b][s][h*64+d] ----
    const float inv0 = 1.0f / l0;
    const float inv1 = 1.0f / l1;
    const int b = bh >> 4, h = bh & 15;
    const int s0 = qt * 128 + wid * 16 + g;
#pragma unroll
    for (int j = 0; j < 8; j++) {
        const int d = j * 8 + q2 * 2;
        {
            const float vx = o[j][0] * inv0, vy = o[j][1] * inv0;
            const float hx = __bfloat162float(__float2bfloat16(vx));
            const float hy = __bfloat162float(__float2bfloat16(vy));
            const size_t off = ((size_t)(b * SEQ + s0)) * DM + h * HD + d;
            *(uint32_t*)&g_chi[off] = pkbf(vx, vy);
            *(uint32_t*)&g_clo[off] = pkbf(vx - hx, vy - hy);
        }
        {
            const float vx = o[j][2] * inv1, vy = o[j][3] * inv1;
            const float hx = __bfloat162float(__float2bfloat16(vx));
            const float hy = __bfloat162float(__float2bfloat16(vy));
            const size_t off = ((size_t)(b * SEQ + s0 + 8)) * DM + h * HD + d;
            *(uint32_t*)&g_chi[off] = pkbf(vx, vy);
            *(uint32_t*)&g_clo[off] = pkbf(vx - hx, vy - hy);
        }
    }
}

// =============================================================================
extern "C" void kernel_launch(void* const* d_in, const int* in_sizes, int n_in,
                              void* d_out, int out_size)
{
    (void)in_sizes; (void)n_in; (void)out_size;
    const float* x  = (const float*)d_in[0];
    const float* Wq = (const float*)d_in[1];
    const float* bq = (const float*)d_in[2];
    const float* Wk = (const float*)d_in[3];
    const float* bk = (const float*)d_in[4];
    const float* Wv = (const float*)d_in[5];
    const float* bv = (const float*)d_in[6];
    const float* Wo = (const float*)d_in[7];
    const float* bo = (const float*)d_in[8];
    float* out = (float*)d_out;

    cudaFuncSetAttribute(k_attn, cudaFuncAttributeMaxDynamicSharedMemorySize,
                         ATT_SMEM_BYTES);

    // 1) weight transpose + split, input split
    k_wT<<<dim3(32, 32, 4), 256>>>(Wq, Wk, Wv, Wo);
    k_split<<<(MROWS * DM) / 1024, 256>>>(x);

    // 2) QKV projections (mma.sync), write split bf16 q/k/v
    k_gemm<<<dim3(DM / 128, MROWS / 128, 3), 256>>>(bq, bk, bv, nullptr, 0);

    // 3) flash attention (mma.sync), writes split bf16 ctx
    k_attn<<<dim3(SEQ / 128, NBH), 256, ATT_SMEM_BYTES>>>();

    // 4) output projection (mma.sync)
    k_gemm<<<dim3(DM / 128, MROWS / 128, 1), 256>>>(bo, bo, bo, out, 3);
}

// round 6
// speedup vs baseline: 3.2802x; 1.0815x over previous
#include <cuda_runtime.h>
#include <cuda_bf16.h>
#include <math.h>
#include <stdint.h>

#define BATCH 4
#define SEQ   2048
#define DM    1024
#define NH    16
#define HD    64
#define MROWS (BATCH*SEQ)      // 8192
#define NBH   (BATCH*NH)       // 64

// ---------------- scratch (device globals: allocation-free rule) -------------
__device__ __nv_bfloat16 g_xhi[(size_t)MROWS * DM];
__device__ __nv_bfloat16 g_xlo[(size_t)MROWS * DM];
__device__ __nv_bfloat16 g_chi[(size_t)MROWS * DM];     // ctx split
__device__ __nv_bfloat16 g_clo[(size_t)MROWS * DM];
__device__ __nv_bfloat16 g_wThi[(size_t)4 * DM * DM];   // W^T [n][k]
__device__ __nv_bfloat16 g_wTlo[(size_t)4 * DM * DM];
__device__ __nv_bfloat16 g_qhi[(size_t)NBH * SEQ * HD]; // [bh][s][64]
__device__ __nv_bfloat16 g_qlo[(size_t)NBH * SEQ * HD];
__device__ __nv_bfloat16 g_khi[(size_t)NBH * SEQ * HD];
__device__ __nv_bfloat16 g_klo[(size_t)NBH * SEQ * HD];
__device__ __nv_bfloat16 g_vhi[(size_t)NBH * SEQ * HD];
__device__ __nv_bfloat16 g_vlo[(size_t)NBH * SEQ * HD];

// ======================= asm helpers =========================================
__device__ __forceinline__ void ldm_x4(uint32_t addr, uint32_t* r) {
    asm volatile("ldmatrix.sync.aligned.m8n8.x4.shared.b16 {%0,%1,%2,%3}, [%4];"
                 : "=r"(r[0]), "=r"(r[1]), "=r"(r[2]), "=r"(r[3]) : "r"(addr));
}
__device__ __forceinline__ void ldm_x4_t(uint32_t addr, uint32_t* r) {
    asm volatile("ldmatrix.sync.aligned.m8n8.x4.trans.shared.b16 {%0,%1,%2,%3}, [%4];"
                 : "=r"(r[0]), "=r"(r[1]), "=r"(r[2]), "=r"(r[3]) : "r"(addr));
}
__device__ __forceinline__ void mma_bf16(float* c, const uint32_t* a,
                                         uint32_t b0, uint32_t b1) {
    asm volatile(
        "mma.sync.aligned.m16n8k16.row.col.f32.bf16.bf16.f32 "
        "{%0,%1,%2,%3}, {%4,%5,%6,%7}, {%8,%9}, {%0,%1,%2,%3};"
        : "+f"(c[0]), "+f"(c[1]), "+f"(c[2]), "+f"(c[3])
        : "r"(a[0]), "r"(a[1]), "r"(a[2]), "r"(a[3]), "r"(b0), "r"(b1));
}
__device__ __forceinline__ uint32_t pkbf(float x, float y) {
    __nv_bfloat162 t = __floats2bfloat162_rn(x, y);
    return *(uint32_t*)&t;
}
__device__ __forceinline__ void cp16(uint32_t dst, const void* src) {
    asm volatile("cp.async.cg.shared.global [%0], [%1], 16;"
                 :: "r"(dst), "l"(src) : "memory");
}
#define CP_COMMIT() asm volatile("cp.async.commit_group;" ::: "memory")
#define CP_WAIT1()  asm volatile("cp.async.wait_group 1;" ::: "memory")
#define CP_WAIT0()  asm volatile("cp.async.wait_group 0;" ::: "memory")

// =============================================================================
// split fp32 x -> hi/lo bf16
// =============================================================================
__global__ __launch_bounds__(256) void k_split(const float* __restrict__ x)
{
    const size_t i = ((size_t)blockIdx.x * 256 + threadIdx.x) * 4;
    float4 v = *(const float4*)(x + i);
    float vv[4] = {v.x, v.y, v.z, v.w};
    __nv_bfloat16 h[4], l[4];
#pragma unroll
    for (int u = 0; u < 4; u++) {
        h[u] = __float2bfloat16(vv[u]);
        l[u] = __float2bfloat16(vv[u] - __bfloat162float(h[u]));
    }
    *(uint2*)(g_xhi + i) = *(uint2*)h;
    *(uint2*)(g_xlo + i) = *(uint2*)l;
}

// =============================================================================
// transpose + split weights: W [k][n] fp32 -> WT hi/lo [n][k] bf16
// =============================================================================
__global__ __launch_bounds__(256) void k_wT(
    const float* __restrict__ Wq, const float* __restrict__ Wk,
    const float* __restrict__ Wv, const float* __restrict__ Wo)
{
    const int z = blockIdx.z;
    const float* __restrict__ W = (z == 0) ? Wq : (z == 1) ? Wk : (z == 2) ? Wv : Wo;
    __nv_bfloat16* __restrict__ Th = g_wThi + (size_t)z * DM * DM;
    __nv_bfloat16* __restrict__ Tl = g_wTlo + (size_t)z * DM * DM;

    __shared__ float t[32][33];
    const int bk = blockIdx.y * 32, bn = blockIdx.x * 32;
    const int tx = threadIdx.x & 31, ty = threadIdx.x >> 5;

#pragma unroll
    for (int i = 0; i < 4; i++)
        t[ty + i * 8][tx] = W[(size_t)(bk + ty + i * 8) * DM + bn + tx];
    __syncthreads();
#pragma unroll
    for (int i = 0; i < 4; i++) {
        const float v = t[tx][ty + i * 8];
        const __nv_bfloat16 h = __float2bfloat16(v);
        const size_t o = (size_t)(bn + ty + i * 8) * DM + bk + tx;
        Th[o] = h;
        Tl[o] = __float2bfloat16(v - __bfloat162float(h));
    }
}

// =============================================================================
// mma.sync bf16-split GEMM, 128x128 block, BK=32, cp.async 2-stage pipeline.
// mode<3: write q/k/v split bf16 permuted [bh][s][64].  mode 3: fp32 out.
// =============================================================================
#define PITCH 40
#define GSTG  (4 * 128 * PITCH)                  // elems per stage = 20480
#define GEMM_SMEM_BYTES (2 * GSTG * 2)           // 81920

__global__ __launch_bounds__(256) void k_gemm(
    const float* __restrict__ b0p, const float* __restrict__ b1p,
    const float* __restrict__ b2p, float* __restrict__ finalOut, int modeBase)
{
    extern __shared__ __nv_bfloat16 smg[];
    const uint32_t aBase = (uint32_t)__cvta_generic_to_shared(smg);

    const int z = blockIdx.z;
    const int mode = modeBase + z;
    const __nv_bfloat16* __restrict__ Ahi = (mode < 3) ? g_xhi : g_chi;
    const __nv_bfloat16* __restrict__ Alo = (mode < 3) ? g_xlo : g_clo;
    const int wsel = (mode < 3) ? z : 3;
    const __nv_bfloat16* __restrict__ Bhi = g_wThi + (size_t)wsel * DM * DM;
    const __nv_bfloat16* __restrict__ Blo = g_wTlo + (size_t)wsel * DM * DM;
    const float* __restrict__ bias = (mode == 0) ? b0p : (mode == 1) ? b1p
                                    : (mode == 2) ? b2p : b0p;

    const int bm = blockIdx.y * 128;
    const int bn = blockIdx.x * 128;
    const int tid = threadIdx.x;
    const int wid = tid >> 5;
    const int lane = tid & 31;
    const int wy = wid >> 1;
    const int wx = wid & 1;

    const uint32_t lmo = (uint32_t)((lane & 15) * PITCH + (lane >> 4) * 8);

    // loader constants
    const int lr  = tid >> 2;            // 0..63 -> rows lr, lr+64 via it
    const int lsg = (tid & 3) * 8;       // elem offset in row

    float acc[2][8][4];
#pragma unroll
    for (int a = 0; a < 2; a++)
#pragma unroll
        for (int b = 0; b < 8; b++)
#pragma unroll
            for (int c = 0; c < 4; c++) acc[a][b][c] = 0.f;

    // -------- pipelined loop --------
    auto issue = [&](int kc, int stg) {
        const int k0 = kc * 32;
        const uint32_t sb = aBase + (uint32_t)(stg * GSTG) * 2;
#pragma unroll
        for (int it = 0; it < 2; it++) {
            const int r = lr + it * 64;
            const size_t gA = (size_t)(bm + r) * DM + k0 + lsg;
            const size_t gB = (size_t)(bn + r) * DM + k0 + lsg;
            const uint32_t so = (uint32_t)(r * PITCH + lsg) * 2;
            cp16(sb + so,                    Ahi + gA);
            cp16(sb + 5120 * 2 + so,         Alo + gA);
            cp16(sb + 10240 * 2 + so,        Bhi + gB);
            cp16(sb + 15360 * 2 + so,        Blo + gB);
        }
    };

    issue(0, 0);
    CP_COMMIT();

    for (int kc = 0; kc < 32; kc++) {
        const int cur = kc & 1;
        if (kc + 1 < 32) {
            issue(kc + 1, (kc + 1) & 1);
            CP_COMMIT();
            CP_WAIT1();
        } else {
            CP_WAIT0();
        }
        __syncthreads();

        const uint32_t sb = aBase + (uint32_t)(cur * GSTG) * 2;
        const uint32_t aAhi = sb;
        const uint32_t aAlo = sb + 5120 * 2;
        const uint32_t aBhi = sb + 10240 * 2;
        const uint32_t aBlo = sb + 15360 * 2;

#pragma unroll
        for (int ks = 0; ks < 2; ks++) {
            uint32_t ahi[2][4], alo[2][4], bhi[4][4], blo[4][4];
#pragma unroll
            for (int mt = 0; mt < 2; mt++) {
                const uint32_t org = (uint32_t)((wy * 32 + mt * 16) * PITCH + ks * 16);
                ldm_x4(aAhi + (org + lmo) * 2, ahi[mt]);
                ldm_x4(aAlo + (org + lmo) * 2, alo[mt]);
            }
#pragma unroll
            for (int np = 0; np < 4; np++) {
                const uint32_t org = (uint32_t)((wx * 64 + np * 16) * PITCH + ks * 16);
                ldm_x4(aBhi + (org + lmo) * 2, bhi[np]);
                ldm_x4(aBlo + (org + lmo) * 2, blo[np]);
            }
#pragma unroll
            for (int mt = 0; mt < 2; mt++) {
#pragma unroll
                for (int np = 0; np < 4; np++) {
                    mma_bf16(acc[mt][np * 2 + 0], ahi[mt], bhi[np][0], bhi[np][2]);
                    mma_bf16(acc[mt][np * 2 + 1], ahi[mt], bhi[np][1], bhi[np][3]);
                    mma_bf16(acc[mt][np * 2 + 0], alo[mt], bhi[np][0], bhi[np][2]);
                    mma_bf16(acc[mt][np * 2 + 1], alo[mt], bhi[np][1], bhi[np][3]);
                    mma_bf16(acc[mt][np * 2 + 0], ahi[mt], blo[np][0], blo[np][2]);
                    mma_bf16(acc[mt][np * 2 + 1], ahi[mt], blo[np][1], blo[np][3]);
                }
            }
        }
        __syncthreads();
    }

    // epilogue
    const int g   = lane >> 2;
    const int tig = lane & 3;
#pragma unroll
    for (int mt = 0; mt < 2; mt++) {
        const int row0 = bm + wy * 32 + mt * 16 + g;
#pragma unroll
        for (int nf = 0; nf < 8; nf++) {
            const int col = bn + wx * 64 + nf * 8 + tig * 2;
            const float* ac = acc[mt][nf];
            const float bx = bias[col], by = bias[col + 1];
            if (mode < 3) {
                __nv_bfloat16* __restrict__ ohi = (mode == 0) ? g_qhi : (mode == 1) ? g_khi : g_vhi;
                __nv_bfloat16* __restrict__ olo = (mode == 0) ? g_qlo : (mode == 1) ? g_klo : g_vlo;
                const int h = col >> 6, dh = col & 63;
#pragma unroll
                for (int rr = 0; rr < 2; rr++) {
                    const int row = row0 + rr * 8;
                    const int b = row >> 11, s = row & 2047;
                    const float vx = ac[rr * 2 + 0] + bx;
                    const float vy = ac[rr * 2 + 1] + by;
                    const float hx = __bfloat162float(__float2bfloat16(vx));
                    const float hy = __bfloat162float(__float2bfloat16(vy));
                    const size_t o = (((size_t)(b * NH + h)) * SEQ + s) * HD + dh;
                    *(uint32_t*)&ohi[o] = pkbf(vx, vy);
                    *(uint32_t*)&olo[o] = pkbf(vx - hx, vy - hy);
                }
            } else {
#pragma unroll
                for (int rr = 0; rr < 2; rr++) {
                    const int row = row0 + rr * 8;
                    float2 v = make_float2(ac[rr * 2 + 0] + bx, ac[rr * 2 + 1] + by);
                    *(float2*)&finalOut[(size_t)row * DM + col] = v;
                }
            }
        }
    }
}

// =============================================================================
// Flash attention on mma.sync, split bf16, Q-tile 128 x KV-tile 64,
// cp.async 2-stage K/V pipeline.  Writes ctx split bf16.
// =============================================================================
#define APITCH 72
#define AQ_ELEMS (128 * APITCH)          // 9216
#define ASTG     (4 * 64 * APITCH)       // 18432 elems per KV stage
#define ATT_SMEM_BYTES ((2 * AQ_ELEMS + 2 * ASTG) * 2)   // 110592

__global__ __launch_bounds__(256) void k_attn()
{
    extern __shared__ __nv_bfloat16 smb[];
    const uint32_t aBase = (uint32_t)__cvta_generic_to_shared(smb);
    const uint32_t aQhi = aBase;
    const uint32_t aQlo = aBase + AQ_ELEMS * 2;

    const int bh  = blockIdx.y;
    const int qt  = (int)gridDim.x - 1 - (int)blockIdx.x;  // heavy first
    const int tid = threadIdx.x;
    const int wid = tid >> 5;
    const int lane = tid & 31;
    const int g   = lane >> 2;
    const int q2  = lane & 3;

    const __nv_bfloat16* __restrict__ Qhi = g_qhi + (size_t)bh * SEQ * HD;
    const __nv_bfloat16* __restrict__ Qlo = g_qlo + (size_t)bh * SEQ * HD;
    const __nv_bfloat16* __restrict__ Khi = g_khi + (size_t)bh * SEQ * HD;
    const __nv_bfloat16* __restrict__ Klo = g_klo + (size_t)bh * SEQ * HD;
    const __nv_bfloat16* __restrict__ Vhi = g_vhi + (size_t)bh * SEQ * HD;
    const __nv_bfloat16* __restrict__ Vlo = g_vlo + (size_t)bh * SEQ * HD;

    // load Q tile (128 x 64) via cp.async too (group 0 shared with KV stage0)
#pragma unroll
    for (int it = 0; it < 4; it++) {
        const int idx = it * 256 + tid;
        const int r  = idx >> 3;
        const int c8 = (idx & 7) * 8;
        const size_t gsrc = (size_t)(qt * 128 + r) * HD + c8;
        const uint32_t so = (uint32_t)(r * APITCH + c8) * 2;
        cp16(aQhi + so, Qhi + gsrc);
        cp16(aQlo + so, Qlo + gsrc);
    }

    const uint32_t lmo = (uint32_t)((lane & 15) * APITCH + (lane >> 4) * 8);
    const int lr  = tid >> 3;            // 0..31 (rows lr, lr+32)
    const int lc8 = (tid & 7) * 8;

    auto issueKV = [&](int kb, int stg) {
        const uint32_t sb = aBase + (uint32_t)(2 * AQ_ELEMS + stg * ASTG) * 2;
#pragma unroll
        for (int it = 0; it < 2; it++) {
            const int r = lr + it * 32;
            const size_t gsrc = (size_t)(kb * 64 + r) * HD + lc8;
            const uint32_t so = (uint32_t)(r * APITCH + lc8) * 2;
            cp16(sb + so,                      Khi + gsrc);
            cp16(sb + (64 * APITCH) * 2 + so,  Klo + gsrc);
            cp16(sb + (128 * APITCH) * 2 + so, Vhi + gsrc);
            cp16(sb + (192 * APITCH) * 2 + so, Vlo + gsrc);
        }
    };

    issueKV(0, 0);
    CP_COMMIT();

    float o[8][4];
#pragma unroll
    for (int j = 0; j < 8; j++)
#pragma unroll
        for (int c = 0; c < 4; c++) o[j][c] = 0.f;
    float m0 = -INFINITY, m1 = -INFINITY, l0 = 0.f, l1 = 0.f;

    const int row0 = qt * 128 + wid * 16 + g;
    const int row1 = row0 + 8;
    const float SC = 1.0f / 32.0f;
    const int nkb = 2 * qt + 2;

    for (int kb = 0; kb < nkb; kb++) {
        if (kb + 1 < nkb) {
            issueKV(kb + 1, (kb + 1) & 1);
            CP_COMMIT();
            CP_WAIT1();
        } else {
            CP_WAIT0();
        }
        __syncthreads();

        const uint32_t sb = aBase + (uint32_t)(2 * AQ_ELEMS + (kb & 1) * ASTG) * 2;
        const uint32_t aKhi = sb;
        const uint32_t aKlo = sb + (64 * APITCH) * 2;
        const uint32_t aVhi = sb + (128 * APITCH) * 2;
        const uint32_t aVlo = sb + (192 * APITCH) * 2;

        // ---- S = Q K^T (3-pass split) ----
        float sf[8][4];
#pragma unroll
        for (int j = 0; j < 8; j++)
#pragma unroll
            for (int c = 0; c < 4; c++) sf[j][c] = 0.f;

#pragma unroll
        for (int kc = 0; kc < 4; kc++) {
            uint32_t qh[4], ql[4];
            const uint32_t orgA = (uint32_t)((wid * 16) * APITCH + kc * 16);
            ldm_x4(aQhi + (orgA + lmo) * 2, qh);
            ldm_x4(aQlo + (orgA + lmo) * 2, ql);
#pragma unroll
            for (int np = 0; np < 4; np++) {
                uint32_t kh[4], kl[4];
                const uint32_t orgB = (uint32_t)((np * 16) * APITCH + kc * 16);
                ldm_x4(aKhi + (orgB + lmo) * 2, kh);
                ldm_x4(aKlo + (orgB + lmo) * 2, kl);
                mma_bf16(sf[np * 2 + 0], qh, kh[0], kh[2]);
                mma_bf16(sf[np * 2 + 1], qh, kh[1], kh[3]);
                mma_bf16(sf[np * 2 + 0], ql, kh[0], kh[2]);
                mma_bf16(sf[np * 2 + 1], ql, kh[1], kh[3]);
                mma_bf16(sf[np * 2 + 0], qh, kl[0], kl[2]);
                mma_bf16(sf[np * 2 + 1], qh, kl[1], kl[3]);
            }
        }

        // ---- scale + causal mask ----
#pragma unroll
        for (int j = 0; j < 8; j++) {
            const int col = kb * 64 + j * 8 + q2 * 2;
            sf[j][0] = (col     > row0) ? -INFINITY : sf[j][0] * SC;
            sf[j][1] = (col + 1 > row0) ? -INFINITY : sf[j][1] * SC;
            sf[j][2] = (col     > row1) ? -INFINITY : sf[j][2] * SC;
            sf[j][3] = (col + 1 > row1) ? -INFINITY : sf[j][3] * SC;
        }

        // ---- online softmax ----
        float mx0 = -INFINITY, mx1 = -INFINITY;
#pragma unroll
        for (int j = 0; j < 8; j++) {
            mx0 = fmaxf(mx0, fmaxf(sf[j][0], sf[j][1]));
            mx1 = fmaxf(mx1, fmaxf(sf[j][2], sf[j][3]));
        }
        mx0 = fmaxf(mx0, __shfl_xor_sync(0xffffffff, mx0, 1));
        mx0 = fmaxf(mx0, __shfl_xor_sync(0xffffffff, mx0, 2));
        mx1 = fmaxf(mx1, __shfl_xor_sync(0xffffffff, mx1, 1));
        mx1 = fmaxf(mx1, __shfl_xor_sync(0xffffffff, mx1, 2));
        const float mn0 = fmaxf(m0, mx0);
        const float mn1 = fmaxf(m1, mx1);
        const float esc0 = __expf(m0 - mn0);
        const float esc1 = __expf(m1 - mn1);
        m0 = mn0; m1 = mn1;

        float sum0 = 0.f, sum1 = 0.f;
#pragma unroll
        for (int j = 0; j < 8; j++) {
            sf[j][0] = __expf(sf[j][0] - mn0);
            sf[j][1] = __expf(sf[j][1] - mn0);
            sf[j][2] = __expf(sf[j][2] - mn1);
            sf[j][3] = __expf(sf[j][3] - mn1);
            sum0 += sf[j][0] + sf[j][1];
            sum1 += sf[j][2] + sf[j][3];
        }
        sum0 += __shfl_xor_sync(0xffffffff, sum0, 1);
        sum0 += __shfl_xor_sync(0xffffffff, sum0, 2);
        sum1 += __shfl_xor_sync(0xffffffff, sum1, 1);
        sum1 += __shfl_xor_sync(0xffffffff, sum1, 2);
        l0 = l0 * esc0 + sum0;
        l1 = l1 * esc1 + sum1;

#pragma unroll
        for (int j = 0; j < 8; j++) {
            o[j][0] *= esc0; o[j][1] *= esc0;
            o[j][2] *= esc1; o[j][3] *= esc1;
        }

        // pack P -> split bf16 A fragments
        uint32_t pah[4][4], pal[4][4];
#pragma unroll
        for (int kc = 0; kc < 4; kc++) {
            const int j0 = kc * 2, j1 = kc * 2 + 1;
            float f0 = sf[j0][0], f1 = sf[j0][1], f2 = sf[j0][2], f3 = sf[j0][3];
            float g0 = sf[j1][0], g1 = sf[j1][1], g2 = sf[j1][2], g3 = sf[j1][3];
            pah[kc][0] = pkbf(f0, f1);
            pah[kc][1] = pkbf(f2, f3);
            pah[kc][2] = pkbf(g0, g1);
            pah[kc][3] = pkbf(g2, g3);
            pal[kc][0] = pkbf(f0 - __bfloat162float(__float2bfloat16(f0)),
                              f1 - __bfloat162float(__float2bfloat16(f1)));
            pal[kc][1] = pkbf(f2 - __bfloat162float(__float2bfloat16(f2)),
                              f3 - __bfloat162float(__float2bfloat16(f3)));
            pal[kc][2] = pkbf(g0 - __bfloat162float(__float2bfloat16(g0)),
                              g1 - __bfloat162float(__float2bfloat16(g1)));
            pal[kc][3] = pkbf(g2 - __bfloat162float(__float2bfloat16(g2)),
                              g3 - __bfloat162float(__float2bfloat16(g3)));
        }

        // ---- O += P V (3-pass split) ----
#pragma unroll
        for (int kc = 0; kc < 4; kc++) {
#pragma unroll
            for (int np = 0; np < 4; np++) {
                uint32_t vh[4], vl[4];
                const uint32_t org = (uint32_t)((kc * 16) * APITCH + np * 16);
                ldm_x4_t(aVhi + (org + lmo) * 2, vh);
                ldm_x4_t(aVlo + (org + lmo) * 2, vl);
                mma_bf16(o[np * 2 + 0], pah[kc], vh[0], vh[1]);
                mma_bf16(o[np * 2 + 1], pah[kc], vh[2], vh[3]);
                mma_bf16(o[np * 2 + 0], pal[kc], vh[0], vh[1]);
                mma_bf16(o[np * 2 + 1], pal[kc], vh[2], vh[3]);
                mma_bf16(o[np * 2 + 0], pah[kc], vl[0], vl[1]);
                mma_bf16(o[np * 2 + 1], pah[kc], vl[2], vl[3]);
            }
        }
        __syncthreads();   // all reads of stage done before refill
    }

    // ---- epilogue: normalize + write ctx split bf16 ----
    const float inv0 = 1.0f / l0;
    const float inv1 = 1.0f / l1;
    const int b = bh >> 4, h = bh & 15;
    const int s0 = qt * 128 + wid * 16 + g;
#pragma unroll
    for (int j = 0; j < 8; j++) {
        const int d = j * 8 + q2 * 2;
        {
            const float vx = o[j][0] * inv0, vy = o[j][1] * inv0;
            const float hx = __bfloat162float(__float2bfloat16(vx));
            const float hy = __bfloat162float(__float2bfloat16(vy));
            const size_t off = ((size_t)(b * SEQ + s0)) * DM + h * HD + d;
            *(uint32_t*)&g_chi[off] = pkbf(vx, vy);
            *(uint32_t*)&g_clo[off] = pkbf(vx - hx, vy - hy);
        }
        {
            const float vx = o[j][2] * inv1, vy = o[j][3] * inv1;
            const float hx = __bfloat162float(__float2bfloat16(vx));
            const float hy = __bfloat162float(__float2bfloat16(vy));
            const size_t off = ((size_t)(b * SEQ + s0 + 8)) * DM + h * HD + d;
            *(uint32_t*)&g_chi[off] = pkbf(vx, vy);
            *(uint32_t*)&g_clo[off] = pkbf(vx - hx, vy - hy);
        }
    }
}

// =============================================================================
extern "C" void kernel_launch(void* const* d_in, const int* in_sizes, int n_in,
                              void* d_out, int out_size)
{
    (void)in_sizes; (void)n_in; (void)out_size;
    const float* x  = (const float*)d_in[0];
    const float* Wq = (const float*)d_in[1];
    const float* bq = (const float*)d_in[2];
    const float* Wk = (const float*)d_in[3];
    const float* bk = (const float*)d_in[4];
    const float* Wv = (const float*)d_in[5];
    const float* bv = (const float*)d_in[6];
    const float* Wo = (const float*)d_in[7];
    const float* bo = (const float*)d_in[8];
    float* out = (float*)d_out;

    cudaFuncSetAttribute(k_gemm, cudaFuncAttributeMaxDynamicSharedMemorySize,
                         GEMM_SMEM_BYTES);
    cudaFuncSetAttribute(k_attn, cudaFuncAttributeMaxDynamicSharedMemorySize,
                         ATT_SMEM_BYTES);

    // 1) weight transpose + split, input split
    k_wT<<<dim3(32, 32, 4), 256>>>(Wq, Wk, Wv, Wo);
    k_split<<<(MROWS * DM) / 1024, 256>>>(x);

    // 2) QKV projections (mma.sync + cp.async pipeline)
    k_gemm<<<dim3(DM / 128, MROWS / 128, 3), 256, GEMM_SMEM_BYTES>>>(bq, bk, bv, nullptr, 0);

    // 3) flash attention (mma.sync + cp.async pipeline)
    k_attn<<<dim3(SEQ / 128, NBH), 256, ATT_SMEM_BYTES>>>();

    // 4) output projection
    k_gemm<<<dim3(DM / 128, MROWS / 128, 1), 256, GEMM_SMEM_BYTES>>>(bo, bo, bo, out, 3);
}